// round 10
// baseline (speedup 1.0000x reference)
#include <cuda_runtime.h>
#include <cuda_bf16.h>
#include <cstdint>
#include <cstddef>

// Problem constants
#define L_  6
#define H_  8
#define M_  1024
#define K_  128
#define V_  128
#define F_  4096
#define B_  4
#define Q_  1024
#define T_  1024
#define BQ_ 4096   // B_*Q_

// ===========================================================================
// Low-level helpers (base PTX only — no sm_103a-specific instructions)
// ===========================================================================
__device__ __forceinline__ uint32_t smem_to_u32(const void* p) {
    uint32_t a;
    asm("{ .reg .u64 t; cvta.to.shared.u64 t, %1; cvt.u32.u64 %0, t; }"
        : "=r"(a) : "l"(p));
    return a;
}

__device__ __forceinline__ void cp16(uint32_t dst, const void* src) {
    asm volatile("cp.async.cg.shared.global [%0], [%1], 16;"
                 :: "r"(dst), "l"(__cvta_generic_to_global(src)));
}
__device__ __forceinline__ void cp_commit() { asm volatile("cp.async.commit_group;" ::: "memory"); }
__device__ __forceinline__ void cp_wait0()  { asm volatile("cp.async.wait_group 0;" ::: "memory"); }
__device__ __forceinline__ void cp_wait1()  { asm volatile("cp.async.wait_group 1;" ::: "memory"); }
__device__ __forceinline__ void cp_wait2()  { asm volatile("cp.async.wait_group 2;" ::: "memory"); }

__device__ __forceinline__ void ldsm_x4(uint32_t* r, uint32_t addr) {
    asm volatile("ldmatrix.sync.aligned.m8n8.x4.shared.b16 {%0,%1,%2,%3}, [%4];"
                 : "=r"(r[0]), "=r"(r[1]), "=r"(r[2]), "=r"(r[3]) : "r"(addr));
}

__device__ __forceinline__ void ldsm_x4_t(uint32_t* r, uint32_t addr) {
    asm volatile("ldmatrix.sync.aligned.m8n8.x4.trans.shared.b16 {%0,%1,%2,%3}, [%4];"
                 : "=r"(r[0]), "=r"(r[1]), "=r"(r[2]), "=r"(r[3]) : "r"(addr));
}

__device__ __forceinline__ void mma16816(float* d, const uint32_t* a, const uint32_t* b) {
    asm volatile(
        "mma.sync.aligned.m16n8k16.row.col.f32.bf16.bf16.f32 "
        "{%0,%1,%2,%3}, {%4,%5,%6,%7}, {%8,%9}, {%0,%1,%2,%3};"
        : "+f"(d[0]), "+f"(d[1]), "+f"(d[2]), "+f"(d[3])
        : "r"(a[0]), "r"(a[1]), "r"(a[2]), "r"(a[3]), "r"(b[0]), "r"(b[1]));
}

__device__ __forceinline__ uint32_t pack_bf162(float a, float b) {
    __nv_bfloat162 t;
    t.x = __float2bfloat16(a);
    t.y = __float2bfloat16(b);
    return *(uint32_t*)&t;
}

// ===========================================================================
// Scratch (device globals; no runtime allocation allowed)
// ===========================================================================
__device__ float g_h[(size_t)BQ_ * M_];

// concat qkv weights [l][3072][1024] (rows 0-1023 q, 1024-2047 k, 2048-3071 v)
#define WCAT_SZ ((size_t)L_ * 3072 * 1024)
#define WO_SZ   ((size_t)L_ * 1048576)
#define WFF_SZ  ((size_t)L_ * 4194304)
__device__ __align__(256) __nv_bfloat16 g_wqkvs_h[WCAT_SZ], g_wqkvs_l[WCAT_SZ];
__device__ __align__(256) __nv_bfloat16 g_wqkvc_h[WCAT_SZ], g_wqkvc_l[WCAT_SZ];
__device__ __align__(256) __nv_bfloat16 g_wos_h[WO_SZ], g_wos_l[WO_SZ];
__device__ __align__(256) __nv_bfloat16 g_woc_h[WO_SZ], g_woc_l[WO_SZ];
__device__ __align__(256) __nv_bfloat16 g_w1_h[WFF_SZ], g_w1_l[WFF_SZ];
__device__ __align__(256) __nv_bfloat16 g_w2_h[WFF_SZ], g_w2_l[WFF_SZ];

// bf16 split activations
__device__ __align__(256) __nv_bfloat16 g_nh [(size_t)BQ_ * M_], g_nl [(size_t)BQ_ * M_];
__device__ __align__(256) __nv_bfloat16 g_qkvh[(size_t)BQ_ * 3072], g_qkvl[(size_t)BQ_ * 3072];
__device__ __align__(256) __nv_bfloat16 g_ph [(size_t)BQ_ * M_], g_pl [(size_t)BQ_ * M_];
__device__ __align__(256) __nv_bfloat16 g_eh [(size_t)B_ * T_ * M_], g_el [(size_t)B_ * T_ * M_];
__device__ __align__(256) __nv_bfloat16 g_sh [(size_t)BQ_ * F_], g_sl [(size_t)BQ_ * F_];

// mask bias arrays: [B][Q][T] bf16 = max(tmask,qtmask) * (-1e6/sqrt(128))
__device__ __align__(256) __nv_bfloat16 g_bias_s[(size_t)B_ * Q_ * T_];
__device__ __align__(256) __nv_bfloat16 g_bias_c[(size_t)B_ * Q_ * T_];

// ===========================================================================
// Block reductions (blockDim.x == 256)
// ===========================================================================
__device__ __forceinline__ float block_sum(float v) {
    __shared__ float sh[8];
    #pragma unroll
    for (int o = 16; o > 0; o >>= 1) v += __shfl_xor_sync(0xffffffffu, v, o);
    __syncthreads();
    if ((threadIdx.x & 31) == 0) sh[threadIdx.x >> 5] = v;
    __syncthreads();
    float t = 0.f;
    #pragma unroll
    for (int i = 0; i < 8; ++i) t += sh[i];
    return t;
}

// ===========================================================================
// Merged batched transpose + bf16 hi/lo split (ONE launch for all weights).
// ===========================================================================
struct TSDesc {
    const float* src;
    __nv_bfloat16 *hi, *lo;
    int R, C, zs;
    long long s1, s2, s3;
    int tiles, cx, cy;
};
struct TSAll { TSDesc d[10]; };

__global__ void __launch_bounds__(256)
tsplit_all_k(TSAll a)
{
    __shared__ float t[32][33];
    int tix = blockIdx.x;
    int i = 0;
    while (tix >= a.d[i].tiles) { tix -= a.d[i].tiles; ++i; }
    const TSDesc& de = a.d[i];
    const int cxy = de.cx * de.cy;
    const int z = tix / cxy;
    const int rr = tix - z * cxy;
    const int by = rr / de.cx;
    const int bx = rr - by * de.cx;

    const long long sbase = (long long)z * de.R * de.C;
    const long long dbase = (long long)(z >> de.zs) * de.s1 +
                            (long long)(z & ((1 << de.zs) - 1)) * de.s2 + de.s3;
    const int c0 = bx << 5, r0 = by << 5;
    const int tx = threadIdx.x & 31, ty = threadIdx.x >> 5;
    #pragma unroll
    for (int k = 0; k < 4; ++k) {
        int r = r0 + ty + k * 8;
        t[ty + k * 8][tx] = de.src[sbase + (long long)r * de.C + c0 + tx];
    }
    __syncthreads();
    #pragma unroll
    for (int k = 0; k < 4; ++k) {
        int c = c0 + ty + k * 8;
        float v = t[tx][ty + k * 8];
        __nv_bfloat16 h = __float2bfloat16(v);
        long long o = dbase + (long long)c * de.R + r0 + tx;
        de.hi[o] = h;
        de.lo[o] = __float2bfloat16(v - __bfloat162float(h));
    }
}

// ===========================================================================
// Elementwise bf16 hi/lo split (vectorized by 4)
// ===========================================================================
__global__ void __launch_bounds__(256)
split_k(const float* __restrict__ x, __nv_bfloat16* __restrict__ hi,
        __nv_bfloat16* __restrict__ lo, int n4)
{
    int i = blockIdx.x * 256 + threadIdx.x;
    if (i >= n4) return;
    float4 v = ((const float4*)x)[i];
    __nv_bfloat16 h[4], l[4];
    h[0] = __float2bfloat16(v.x); l[0] = __float2bfloat16(v.x - __bfloat162float(h[0]));
    h[1] = __float2bfloat16(v.y); l[1] = __float2bfloat16(v.y - __bfloat162float(h[1]));
    h[2] = __float2bfloat16(v.z); l[2] = __float2bfloat16(v.z - __bfloat162float(h[2]));
    h[3] = __float2bfloat16(v.w); l[3] = __float2bfloat16(v.w - __bfloat162float(h[3]));
    *(uint2*)(hi + 4 * (size_t)i) = *(uint2*)h;
    *(uint2*)(lo + 4 * (size_t)i) = *(uint2*)l;
}

// ===========================================================================
// Mask bias build (BOTH arrays in one launch; blockIdx.z selects).
// ===========================================================================
__global__ void __launch_bounds__(256)
bias_all_k(const float* __restrict__ pmask, const float* __restrict__ qtself,
           const float* __restrict__ qtcross,
           __nv_bfloat16* __restrict__ bs, __nv_bfloat16* __restrict__ bc)
{
    const bool self = (blockIdx.z == 0);
    const float* tmask = self ? pmask : nullptr;
    const float* qtm   = self ? qtself : qtcross;
    __nv_bfloat16* out = self ? bs : bc;
    const long long i2 = ((long long)blockIdx.x * 256 + threadIdx.x) * 2;
    const int t = (int)(i2 & 1023);
    const int b = (int)(i2 >> 20);
    float m0 = qtm[i2], m1 = qtm[i2 + 1];
    if (tmask) {
        m0 = fmaxf(m0, tmask[b * 1024 + t]);
        m1 = fmaxf(m1, tmask[b * 1024 + t + 1]);
    }
    const float c = -88388.34765f;   // -1e6 / sqrt(128)
    __nv_bfloat162 o;
    o.x = __float2bfloat16(m0 * c);
    o.y = __float2bfloat16(m1 * c);
    *(__nv_bfloat162*)(out + i2) = o;
}

// ===========================================================================
// Plain fp32 copy
// ===========================================================================
__global__ void __launch_bounds__(256)
copy_k(const float4* __restrict__ s, float4* __restrict__ d, int n4)
{
    int i = blockIdx.x * 256 + threadIdx.x;
    if (i < n4) d[i] = s[i];
}

// ===========================================================================
// LayerNorm over M=1024, emitting bf16 hi/lo split. One block per row.
// ===========================================================================
__global__ void __launch_bounds__(256)
layernorm_split_k(const float* __restrict__ x, const float* __restrict__ g,
                  const float* __restrict__ b,
                  __nv_bfloat16* __restrict__ hi, __nv_bfloat16* __restrict__ lo)
{
    const int row = blockIdx.x;
    const float* xp = x + (size_t)row * M_;
    const int c = threadIdx.x << 2;
    float4 d = *(const float4*)(xp + c);
    float s  = d.x + d.y + d.z + d.w;
    float ss = d.x * d.x + d.y * d.y + d.z * d.z + d.w * d.w;
    s  = block_sum(s);
    ss = block_sum(ss);
    const float mean = s * (1.f / M_);
    const float var  = ss * (1.f / M_) - mean * mean;
    const float inv  = rsqrtf(var + 1e-5f);
    float4 g4 = *(const float4*)(g + c);
    float4 b4 = *(const float4*)(b + c);
    float o[4];
    o[0] = (d.x - mean) * inv * g4.x + b4.x;
    o[1] = (d.y - mean) * inv * g4.y + b4.y;
    o[2] = (d.z - mean) * inv * g4.z + b4.z;
    o[3] = (d.w - mean) * inv * g4.w + b4.w;
    __nv_bfloat16 h[4], l[4];
    #pragma unroll
    for (int i = 0; i < 4; ++i) {
        h[i] = __float2bfloat16(o[i]);
        l[i] = __float2bfloat16(o[i] - __bfloat162float(h[i]));
    }
    *(uint2*)(hi + (size_t)row * M_ + c) = *(uint2*)h;
    *(uint2*)(lo + (size_t)row * M_ + c) = *(uint2*)l;
}

// ===========================================================================
// Fused flash attention (bf16x3, fp32 softmax/accum).  (unchanged from R6)
// ===========================================================================
#define FL_QP  272
#define FL_SQH 0
#define FL_SQL 17408
#define FL_SKH 34816
#define FL_SKL 52224
#define FL_SVH 69632
#define FL_SVL 87040
#define FL_SMEM 104448

__global__ void __launch_bounds__(128)
flash_k(const __nv_bfloat16* __restrict__ qkvh, const __nv_bfloat16* __restrict__ qkvl,
        const __nv_bfloat16* __restrict__ bias,
        __nv_bfloat16* __restrict__ ph, __nv_bfloat16* __restrict__ pl)
{
    extern __shared__ __align__(128) char smem[];
    const int tid = threadIdx.x, wid = tid >> 5, lane = tid & 31;
    const int bh = blockIdx.y, b = bh >> 3, h = bh & 7;
    const int q0 = blockIdx.x << 6;
    const uint32_t sb = smem_to_u32(smem);
    const int lr = lane >> 2, lq = lane & 3;
    const int qrow0 = b * 1024 + q0 + wid * 16 + lr;

    {
        int seg = tid;
        #pragma unroll
        for (int i = 0; i < 8; ++i, seg += 128) {
            int r = seg >> 4, s = seg & 15;
            uint32_t d = sb + FL_SQH + r * FL_QP + s * 16;
            long long g = (long long)(b * 1024 + q0 + r) * 3072 + h * 128 + s * 8;
            cp16(d, qkvh + g);
            cp16(d + (FL_SQL - FL_SQH), qkvl + g);
        }
        cp_commit(); cp_wait0();
    }
    __syncthreads();

    const uint32_t aoff  = ((lane & 7) + ((lane >> 3) & 1) * 8) * FL_QP + ((lane >> 4) & 1) * 16;
    const uint32_t boffK = ((lane & 7) + ((lane >> 4) & 1) * 8) * FL_QP + ((lane >> 3) & 1) * 16;

    uint32_t qfh[8][4], qfl[8][4];
    #pragma unroll
    for (int ks = 0; ks < 8; ++ks) {
        uint32_t ad = sb + FL_SQH + (wid * 16) * FL_QP + ks * 32 + aoff;
        ldsm_x4(qfh[ks], ad);
        ldsm_x4(qfl[ks], ad + (FL_SQL - FL_SQH));
    }

    float accO[16][4];
    #pragma unroll
    for (int i = 0; i < 16; ++i)
        #pragma unroll
        for (int j = 0; j < 4; ++j) accO[i][j] = 0.f;
    float mrow[2] = {-3.0e38f, -3.0e38f};
    float lrow[2] = {0.f, 0.f};
    const float inv = 0.08838834764831845f;
    const float L2E = 1.4426950408889634f;

    for (int tc = 0; tc < 16; ++tc) {
        const int t0 = tc << 6;

        uint32_t braw[16];
        int alive = 0;
        #pragma unroll
        for (int nf = 0; nf < 8; ++nf) {
            const int t = t0 + nf * 8 + lq * 2;
            #pragma unroll
            for (int i2 = 0; i2 < 2; ++i2) {
                uint32_t v = *(const uint32_t*)(bias + ((long long)(qrow0 + 8 * i2) << 10) + t);
                braw[nf * 2 + i2] = v;
                __nv_bfloat162 bb = *(__nv_bfloat162*)&v;
                if (__bfloat162float(bb.x) > -1.0e4f || __bfloat162float(bb.y) > -1.0e4f)
                    alive = 1;
            }
        }
        if (!__syncthreads_or(alive)) continue;

        int seg = tid;
        #pragma unroll
        for (int i = 0; i < 8; ++i, seg += 128) {
            int r = seg >> 4, s = seg & 15;
            long long g = (long long)(b * 1024 + t0 + r) * 3072 + h * 128 + s * 8;
            uint32_t d = sb + FL_SKH + r * FL_QP + s * 16;
            cp16(d, qkvh + g + 1024);
            cp16(d + (FL_SKL - FL_SKH), qkvl + g + 1024);
            uint32_t dv = sb + FL_SVH + r * FL_QP + s * 16;
            cp16(dv, qkvh + g + 2048);
            cp16(dv + (FL_SVL - FL_SVH), qkvl + g + 2048);
        }
        cp_commit(); cp_wait0();
        __syncthreads();

        float accS[8][4];
        #pragma unroll
        for (int i = 0; i < 8; ++i)
            #pragma unroll
            for (int j = 0; j < 4; ++j) accS[i][j] = 0.f;
        #pragma unroll
        for (int ks = 0; ks < 8; ++ks) {
            #pragma unroll
            for (int nt = 0; nt < 4; ++nt) {
                uint32_t bh4[4], bl4[4];
                uint32_t bd = sb + FL_SKH + (nt * 16) * FL_QP + ks * 32 + boffK;
                ldsm_x4(bh4, bd);
                ldsm_x4(bl4, bd + (FL_SKL - FL_SKH));
                mma16816(accS[2 * nt],     qfh[ks], &bh4[0]);
                mma16816(accS[2 * nt + 1], qfh[ks], &bh4[2]);
                mma16816(accS[2 * nt],     qfh[ks], &bl4[0]);
                mma16816(accS[2 * nt + 1], qfh[ks], &bl4[2]);
                mma16816(accS[2 * nt],     qfl[ks], &bh4[0]);
                mma16816(accS[2 * nt + 1], qfl[ks], &bh4[2]);
            }
        }

        float pm[2] = {-3.0e38f, -3.0e38f};
        #pragma unroll
        for (int nf = 0; nf < 8; ++nf) {
            #pragma unroll
            for (int i2 = 0; i2 < 2; ++i2) {
                __nv_bfloat162 bb = *(__nv_bfloat162*)&braw[nf * 2 + i2];
                float s0 = accS[nf][i2 * 2 + 0] * inv + __bfloat162float(bb.x);
                float s1 = accS[nf][i2 * 2 + 1] * inv + __bfloat162float(bb.y);
                accS[nf][i2 * 2 + 0] = s0;
                accS[nf][i2 * 2 + 1] = s1;
                pm[i2] = fmaxf(pm[i2], fmaxf(s0, s1));
            }
        }
        #pragma unroll
        for (int i2 = 0; i2 < 2; ++i2) {
            pm[i2] = fmaxf(pm[i2], __shfl_xor_sync(0xffffffffu, pm[i2], 1));
            pm[i2] = fmaxf(pm[i2], __shfl_xor_sync(0xffffffffu, pm[i2], 2));
            float mnew = fmaxf(mrow[i2], pm[i2]);
            float sc = exp2f((mrow[i2] - mnew) * L2E);
            mrow[i2] = mnew;
            lrow[i2] *= sc;
            #pragma unroll
            for (int nf = 0; nf < 16; ++nf) {
                accO[nf][i2 * 2 + 0] *= sc;
                accO[nf][i2 * 2 + 1] *= sc;
            }
        }
        float psum[2] = {0.f, 0.f};
        #pragma unroll
        for (int nf = 0; nf < 8; ++nf) {
            #pragma unroll
            for (int i2 = 0; i2 < 2; ++i2) {
                float p0 = exp2f((accS[nf][i2 * 2 + 0] - mrow[i2]) * L2E);
                float p1 = exp2f((accS[nf][i2 * 2 + 1] - mrow[i2]) * L2E);
                accS[nf][i2 * 2 + 0] = p0;
                accS[nf][i2 * 2 + 1] = p1;
                psum[i2] += p0 + p1;
            }
        }
        #pragma unroll
        for (int i2 = 0; i2 < 2; ++i2) {
            psum[i2] += __shfl_xor_sync(0xffffffffu, psum[i2], 1);
            psum[i2] += __shfl_xor_sync(0xffffffffu, psum[i2], 2);
            lrow[i2] += psum[i2];
        }

        #pragma unroll
        for (int kk = 0; kk < 4; ++kk) {
            uint32_t pah[4], pal[4];
            #pragma unroll
            for (int half = 0; half < 2; ++half) {
                const float v0 = accS[2 * kk + half][0], v1 = accS[2 * kk + half][1];
                const float v2 = accS[2 * kk + half][2], v3 = accS[2 * kk + half][3];
                pah[0 + half * 2] = pack_bf162(v0, v1);
                pah[1 + half * 2] = pack_bf162(v2, v3);
                __nv_bfloat162 h01 = *(__nv_bfloat162*)&pah[0 + half * 2];
                __nv_bfloat162 h23 = *(__nv_bfloat162*)&pah[1 + half * 2];
                pal[0 + half * 2] = pack_bf162(v0 - __bfloat162float(h01.x),
                                               v1 - __bfloat162float(h01.y));
                pal[1 + half * 2] = pack_bf162(v2 - __bfloat162float(h23.x),
                                               v3 - __bfloat162float(h23.y));
            }
            #pragma unroll
            for (int np = 0; np < 8; ++np) {
                uint32_t vh4[4], vl4[4];
                uint32_t bd = sb + FL_SVH + (kk * 16) * FL_QP + np * 32 + aoff;
                ldsm_x4_t(vh4, bd);
                ldsm_x4_t(vl4, bd + (FL_SVL - FL_SVH));
                mma16816(accO[2 * np],     pah, &vh4[0]);
                mma16816(accO[2 * np + 1], pah, &vh4[2]);
                mma16816(accO[2 * np],     pah, &vl4[0]);
                mma16816(accO[2 * np + 1], pah, &vl4[2]);
                mma16816(accO[2 * np],     pal, &vh4[0]);
                mma16816(accO[2 * np + 1], pal, &vh4[2]);
            }
        }
        __syncthreads();
    }

    float rp[2];
    rp[0] = 1.f / lrow[0];
    rp[1] = 1.f / lrow[1];
    #pragma unroll
    for (int nf = 0; nf < 16; ++nf) {
        #pragma unroll
        for (int i2 = 0; i2 < 2; ++i2) {
            float v0 = accO[nf][i2 * 2 + 0] * rp[i2];
            float v1 = accO[nf][i2 * 2 + 1] * rp[i2];
            long long o = ((long long)(qrow0 + 8 * i2) << 10) + h * 128 + nf * 8 + lq * 2;
            __nv_bfloat162 hh, ll;
            hh.x = __float2bfloat16(v0);
            hh.y = __float2bfloat16(v1);
            ll.x = __float2bfloat16(v0 - __bfloat162float(hh.x));
            ll.y = __float2bfloat16(v1 - __bfloat162float(hh.y));
            *(__nv_bfloat162*)(ph + o) = hh;
            *(__nv_bfloat162*)(pl + o) = ll;
        }
    }
}

// ===========================================================================
// bf16x3 mma.sync GEMM (dense): C[M x N] = A[M x K] * B[N x K]^T
// CTA tile 128x128, BK=16, 8 warps, 4-stage cp.async pipeline.
// Stage = 24KB -> 4 stages = 96KB -> TWO CTAs per SM (launch_bounds(256,2)
// pins regs <= 128 so the register file also fits two CTAs).
// Pitch 48B: rows 0..7 hit disjoint bank quads -> conflict-free ldmatrix.
// ===========================================================================
#define PITCH_B 48
#define TILE_B  (128 * PITCH_B)    // 6144
#define STAGE_B (4 * TILE_B)       // 24576
#define MG_SMEM (4 * STAGE_B)      // 98304

__device__ __forceinline__ void mg_load(
    uint32_t sb, const __nv_bfloat16* __restrict__ Ah, const __nv_bfloat16* __restrict__ Al,
    const __nv_bfloat16* __restrict__ Bh, const __nv_bfloat16* __restrict__ Bl,
    int tid, int m0, int n0, int lda, int ldb, int koff)
{
    const int r = tid >> 1, s = tid & 1;      // 128 rows x 2 16B-segments
    const uint32_t dA = sb + r * PITCH_B + s * 16;
    const long long gA = (long long)(m0 + r) * lda + koff + s * 8;
    cp16(dA,          Ah + gA);
    cp16(dA + TILE_B, Al + gA);
    const uint32_t dB = sb + 2 * TILE_B + r * PITCH_B + s * 16;
    const long long gB = (long long)(n0 + r) * ldb + koff + s * 8;
    cp16(dB,          Bh + gB);
    cp16(dB + TILE_B, Bl + gB);
    cp_commit();
}

template <int EPI, int OUT>
__global__ void __launch_bounds__(256, 2)
mgemm_k(const __nv_bfloat16* __restrict__ Ah, const __nv_bfloat16* __restrict__ Al, int lda,
        const __nv_bfloat16* __restrict__ Bh, const __nv_bfloat16* __restrict__ Bl, int ldb,
        float* Cf, __nv_bfloat16* Ch, __nv_bfloat16* Cl, int ldc,
        const float* __restrict__ resid, int ldr,
        const float* __restrict__ bias,
        const float* __restrict__ rowmask, int Kdim)
{
    extern __shared__ __align__(128) char smem[];
    const int tid = threadIdx.x, wid = tid >> 5, lane = tid & 31;
    const int m0 = blockIdx.y << 7, n0 = blockIdx.x << 7;
    const int wm = (wid >> 1) << 5;
    const int wn = (wid & 1) << 6;
    const uint32_t sb0 = smem_to_u32(smem);

    const uint32_t aoff = ((lane & 7) + ((lane >> 3) & 1) * 8) * PITCH_B + ((lane >> 4) & 1) * 16;
    const uint32_t boff = ((lane & 7) + ((lane >> 4) & 1) * 8) * PITCH_B + ((lane >> 3) & 1) * 16;

    float acc[2][8][4];
    #pragma unroll
    for (int i = 0; i < 2; ++i)
        #pragma unroll
        for (int j = 0; j < 8; ++j)
            #pragma unroll
            for (int k = 0; k < 4; ++k) acc[i][j][k] = 0.f;

    const int NC = Kdim >> 4;   // BK=16; >= 64 at all call sites
    mg_load(sb0,               Ah, Al, Bh, Bl, tid, m0, n0, lda, ldb, 0);
    mg_load(sb0 + STAGE_B,     Ah, Al, Bh, Bl, tid, m0, n0, lda, ldb, 16);
    mg_load(sb0 + 2 * STAGE_B, Ah, Al, Bh, Bl, tid, m0, n0, lda, ldb, 32);

    for (int kt = 0; kt < NC; ++kt) {
        if (kt + 2 < NC)      cp_wait2();
        else if (kt + 1 < NC) cp_wait1();
        else                  cp_wait0();
        __syncthreads();
        if (kt + 3 < NC)
            mg_load(sb0 + (uint32_t)((kt + 3) & 3) * STAGE_B,
                    Ah, Al, Bh, Bl, tid, m0, n0, lda, ldb, (kt + 3) << 4);

        const uint32_t sA = sb0 + (uint32_t)(kt & 3) * STAGE_B;
        const uint32_t sB = sA + 2 * TILE_B;

        uint32_t a_hi[2][4], a_lo[2][4];
        #pragma unroll
        for (int mf = 0; mf < 2; ++mf) {
            uint32_t ad = sA + (wm + mf * 16) * PITCH_B + aoff;
            ldsm_x4(a_hi[mf], ad);
            ldsm_x4(a_lo[mf], ad + TILE_B);
        }
        #pragma unroll
        for (int np = 0; np < 4; ++np) {
            uint32_t b_hi[4], b_lo[4];
            uint32_t bd = sB + (wn + np * 16) * PITCH_B + boff;
            ldsm_x4(b_hi, bd);
            ldsm_x4(b_lo, bd + TILE_B);
            #pragma unroll
            for (int mf = 0; mf < 2; ++mf) {
                mma16816(acc[mf][2 * np],     a_hi[mf], &b_hi[0]);
                mma16816(acc[mf][2 * np + 1], a_hi[mf], &b_hi[2]);
                mma16816(acc[mf][2 * np],     a_hi[mf], &b_lo[0]);
                mma16816(acc[mf][2 * np + 1], a_hi[mf], &b_lo[2]);
                mma16816(acc[mf][2 * np],     a_lo[mf], &b_hi[0]);
                mma16816(acc[mf][2 * np + 1], a_lo[mf], &b_hi[2]);
            }
        }
    }

    const int lr = lane >> 2, lc2 = (lane & 3) << 1;
    #pragma unroll
    for (int mf = 0; mf < 2; ++mf) {
        #pragma unroll
        for (int h2 = 0; h2 < 2; ++h2) {
            const long long r = m0 + wm + mf * 16 + h2 * 8 + lr;
            float mfac = 1.f;
            if (EPI == 1 || EPI == 3) mfac = 1.f - rowmask[r];
            #pragma unroll
            for (int nf = 0; nf < 8; ++nf) {
                float v0 = acc[mf][nf][h2 * 2 + 0];
                float v1 = acc[mf][nf][h2 * 2 + 1];
                const long long c = n0 + wn + nf * 8 + lc2;
                if (EPI >= 2) { v0 += bias[c]; v1 += bias[c + 1]; }
                if (EPI == 2) { v0 = fmaxf(v0, 0.f); v1 = fmaxf(v1, 0.f); }
                if (EPI == 1 || EPI == 3) {
                    float2 rs = *(const float2*)(resid + r * ldr + c);
                    v0 = rs.x + v0 * mfac;
                    v1 = rs.y + v1 * mfac;
                }
                if (OUT == 0) {
                    float2 o; o.x = v0; o.y = v1;
                    *(float2*)(Cf + r * ldc + c) = o;
                } else {
                    __nv_bfloat16 h0 = __float2bfloat16(v0), h1 = __float2bfloat16(v1);
                    __nv_bfloat162 hh, ll;
                    hh.x = h0; hh.y = h1;
                    ll.x = __float2bfloat16(v0 - __bfloat162float(h0));
                    ll.y = __float2bfloat16(v1 - __bfloat162float(h1));
                    *(__nv_bfloat162*)(Ch + r * ldc + c) = hh;
                    *(__nv_bfloat162*)(Cl + r * ldc + c) = ll;
                }
            }
        }
    }
}

// ===========================================================================
// Host orchestration
// ===========================================================================
extern "C" void kernel_launch(void* const* d_in, const int* in_sizes, int n_in,
                              void* d_out, int out_size)
{
    (void)in_sizes; (void)n_in; (void)out_size;

    const float* enc_out = (const float*)d_in[0];
    const float* x       = (const float*)d_in[1];
    const float* pmask   = (const float*)d_in[2];
    const float* qtself  = (const float*)d_in[3];
    const float* qtcross = (const float*)d_in[4];
    const float* swq = (const float*)d_in[5];
    const float* swk = (const float*)d_in[6];
    const float* swv = (const float*)d_in[7];
    const float* swo = (const float*)d_in[8];
    const float* cwq = (const float*)d_in[9];
    const float* cwk = (const float*)d_in[10];
    const float* cwv = (const float*)d_in[11];
    const float* cwo = (const float*)d_in[12];
    const float* w1  = (const float*)d_in[13];
    const float* b1  = (const float*)d_in[14];
    const float* w2  = (const float*)d_in[15];
    const float* b2  = (const float*)d_in[16];
    const float* ln1g = (const float*)d_in[17];
    const float* ln1b = (const float*)d_in[18];
    const float* ln2g = (const float*)d_in[19];
    const float* ln2b = (const float*)d_in[20];
    const float* ln3g = (const float*)d_in[21];
    const float* ln3b = (const float*)d_in[22];

    float* hb;
    cudaGetSymbolAddress((void**)&hb, g_h);

    __nv_bfloat16 *wqkvs_h, *wqkvs_l, *wqkvc_h, *wqkvc_l;
    __nv_bfloat16 *wos_h, *wos_l, *woc_h, *woc_l, *w1h, *w1l, *w2h, *w2l;
    __nv_bfloat16 *nh, *nl, *qkvh, *qkvl, *ph, *pl, *eh, *el, *sh, *sl, *bs, *bc;
    cudaGetSymbolAddress((void**)&wqkvs_h, g_wqkvs_h);
    cudaGetSymbolAddress((void**)&wqkvs_l, g_wqkvs_l);
    cudaGetSymbolAddress((void**)&wqkvc_h, g_wqkvc_h);
    cudaGetSymbolAddress((void**)&wqkvc_l, g_wqkvc_l);
    cudaGetSymbolAddress((void**)&wos_h, g_wos_h); cudaGetSymbolAddress((void**)&wos_l, g_wos_l);
    cudaGetSymbolAddress((void**)&woc_h, g_woc_h); cudaGetSymbolAddress((void**)&woc_l, g_woc_l);
    cudaGetSymbolAddress((void**)&w1h, g_w1_h);    cudaGetSymbolAddress((void**)&w1l, g_w1_l);
    cudaGetSymbolAddress((void**)&w2h, g_w2_h);    cudaGetSymbolAddress((void**)&w2l, g_w2_l);
    cudaGetSymbolAddress((void**)&nh, g_nh);     cudaGetSymbolAddress((void**)&nl, g_nl);
    cudaGetSymbolAddress((void**)&qkvh, g_qkvh); cudaGetSymbolAddress((void**)&qkvl, g_qkvl);
    cudaGetSymbolAddress((void**)&ph, g_ph);     cudaGetSymbolAddress((void**)&pl, g_pl);
    cudaGetSymbolAddress((void**)&eh, g_eh);     cudaGetSymbolAddress((void**)&el, g_el);
    cudaGetSymbolAddress((void**)&sh, g_sh);     cudaGetSymbolAddress((void**)&sl, g_sl);
    cudaGetSymbolAddress((void**)&bs, g_bias_s); cudaGetSymbolAddress((void**)&bc, g_bias_c);

    cudaFuncSetAttribute(mgemm_k<0,1>, cudaFuncAttributeMaxDynamicSharedMemorySize, MG_SMEM);
    cudaFuncSetAttribute(mgemm_k<1,0>, cudaFuncAttributeMaxDynamicSharedMemorySize, MG_SMEM);
    cudaFuncSetAttribute(mgemm_k<2,1>, cudaFuncAttributeMaxDynamicSharedMemorySize, MG_SMEM);
    cudaFuncSetAttribute(mgemm_k<3,0>, cudaFuncAttributeMaxDynamicSharedMemorySize, MG_SMEM);
    cudaFuncSetAttribute(flash_k, cudaFuncAttributeMaxDynamicSharedMemorySize, FL_SMEM);

    // --- launch 1: h = x ---
    copy_k<<<BQ_ * M_ / 4 / 256, 256>>>((const float4*)x, (float4*)hb, BQ_ * M_ / 4);
    // --- launch 2: all weight transposes+splits ---
    {
        const long long sL = 3145728LL;
        const long long sH = 131072LL;
        TSAll a;
        auto set = [&](int i, const float* src, __nv_bfloat16* hi, __nv_bfloat16* lo,
                       int R, int C, int zs, long long s1, long long s2, long long s3, int Z) {
            a.d[i] = { src, hi, lo, R, C, zs, s1, s2, s3, (C / 32) * (R / 32) * Z,
                       C / 32, R / 32 };
        };
        set(0, swq, wqkvs_h, wqkvs_l, M_, K_, 3, sL, sH, 0LL,        L_ * H_);
        set(1, swk, wqkvs_h, wqkvs_l, M_, K_, 3, sL, sH, 1048576LL,  L_ * H_);
        set(2, swv, wqkvs_h, wqkvs_l, M_, K_, 3, sL, sH, 2097152LL,  L_ * H_);
        set(3, cwq, wqkvc_h, wqkvc_l, M_, K_, 3, sL, sH, 0LL,        L_ * H_);
        set(4, cwk, wqkvc_h, wqkvc_l, M_, K_, 3, sL, sH, 1048576LL,  L_ * H_);
        set(5, cwv, wqkvc_h, wqkvc_l, M_, K_, 3, sL, sH, 2097152LL,  L_ * H_);
        set(6, swo, wos_h, wos_l, H_ * V_, M_, 0, 1048576LL, 0LL, 0LL, L_);
        set(7, cwo, woc_h, woc_l, H_ * V_, M_, 0, 1048576LL, 0LL, 0LL, L_);
        set(8, w1,  w1h, w1l, M_, F_, 0, 4194304LL, 0LL, 0LL, L_);
        set(9, w2,  w2h, w2l, F_, M_, 0, 4194304LL, 0LL, 0LL, L_);
        int total = 0;
        for (int i = 0; i < 10; ++i) total += a.d[i].tiles;
        tsplit_all_k<<<total, 256>>>(a);
    }

    const dim3 gQKV(3072 / 128, BQ_ / 128);
    const dim3 gPq (M_ / 128,  BQ_ / 128);
    const dim3 gKV (2048 / 128, BQ_ / 128);
    const dim3 gP  (M_ / 128,  BQ_ / 128);
    const dim3 gF1 (F_ / 128,  BQ_ / 128);
    const dim3 gFL (Q_ / 64, B_ * H_);
    const long long wS  = 3145728LL;
    const size_t wO  = 1048576;
    const size_t wLF = 4194304;

    for (int l = 0; l < L_; ++l) {
        for (int pass = 0; pass < 2; ++pass) {
            const bool self = (pass == 0);
            const float* lng = self ? ln1g : ln2g;
            const float* lnb = self ? ln1b : ln2b;
            __nv_bfloat16* wcat_h = (self ? wqkvs_h : wqkvc_h) + l * wS;
            __nv_bfloat16* wcat_l = (self ? wqkvs_l : wqkvc_l) + l * wS;
            __nv_bfloat16* wo_h = (self ? wos_h : woc_h) + l * wO;
            __nv_bfloat16* wo_l = (self ? wos_l : woc_l) + l * wO;

            // l=0 self: LN is launch #3, QKV mgemm is #4 <- ncu target
            layernorm_split_k<<<BQ_, 256>>>(hb, lng + l * M_, lnb + l * M_, nh, nl);
            if (self) {
                mgemm_k<0,1><<<gQKV, 256, MG_SMEM>>>(nh, nl, M_, wcat_h, wcat_l, M_,
                                                     nullptr, qkvh, qkvl, 3072,
                                                     nullptr, 0, nullptr, nullptr, M_);
            } else {
                mgemm_k<0,1><<<gPq, 256, MG_SMEM>>>(nh, nl, M_, wcat_h, wcat_l, M_,
                                                    nullptr, qkvh, qkvl, 3072,
                                                    nullptr, 0, nullptr, nullptr, M_);
                mgemm_k<0,1><<<gKV, 256, MG_SMEM>>>(eh, el, M_,
                                                    wcat_h + 1048576, wcat_l + 1048576, M_,
                                                    nullptr, qkvh + 1024, qkvl + 1024, 3072,
                                                    nullptr, 0, nullptr, nullptr, M_);
            }
            // deferred prep (first iteration only): mask biases + enc split.
            if (l == 0 && self) {
                dim3 gb(B_ * Q_ * T_ / 2 / 256, 1, 2);
                bias_all_k<<<gb, 256>>>(pmask, qtself, qtcross, bs, bc);
                split_k<<<B_ * T_ * M_ / 4 / 256, 256>>>(enc_out, eh, el, B_ * T_ * M_ / 4);
            }
            flash_k<<<gFL, 128, FL_SMEM>>>(qkvh, qkvl, self ? bs : bc, ph, pl);
            mgemm_k<1,0><<<gP, 256, MG_SMEM>>>(ph, pl, M_, wo_h, wo_l, M_,
                                               hb, nullptr, nullptr, M_,
                                               hb, M_, nullptr, pmask, M_);
        }

        // ---- FFN ----
        layernorm_split_k<<<BQ_, 256>>>(hb, ln3g + l * M_, ln3b + l * M_, nh, nl);
        mgemm_k<2,1><<<gF1, 256, MG_SMEM>>>(nh, nl, M_, w1h + l * wLF, w1l + l * wLF, M_,
                                            nullptr, sh, sl, F_,
                                            nullptr, 0, b1 + l * F_, nullptr, M_);
        float* cdst = (l == L_ - 1) ? (float*)d_out : hb;
        mgemm_k<3,0><<<gP, 256, MG_SMEM>>>(sh, sl, F_, w2h + l * wLF, w2l + l * wLF, F_,
                                           cdst, nullptr, nullptr, M_,
                                           hb, M_, b2 + l * M_, pmask, F_);
    }
}

// round 12
// speedup vs baseline: 1.3413x; 1.3413x over previous
#include <cuda_runtime.h>
#include <cuda_fp16.h>
#include <cstdint>
#include <cstddef>

// Problem constants
#define L_  6
#define H_  8
#define M_  1024
#define K_  128
#define V_  128
#define F_  4096
#define B_  4
#define Q_  1024
#define T_  1024
#define BQ_ 4096   // B_*Q_

// ===========================================================================
// Low-level helpers (base PTX only)
// ===========================================================================
__device__ __forceinline__ uint32_t smem_to_u32(const void* p) {
    uint32_t a;
    asm("{ .reg .u64 t; cvta.to.shared.u64 t, %1; cvt.u32.u64 %0, t; }"
        : "=r"(a) : "l"(p));
    return a;
}

__device__ __forceinline__ void cp16(uint32_t dst, const void* src) {
    asm volatile("cp.async.cg.shared.global [%0], [%1], 16;"
                 :: "r"(dst), "l"(__cvta_generic_to_global(src)));
}
__device__ __forceinline__ void cp_commit() { asm volatile("cp.async.commit_group;" ::: "memory"); }
__device__ __forceinline__ void cp_wait0()  { asm volatile("cp.async.wait_group 0;" ::: "memory"); }
__device__ __forceinline__ void cp_wait1()  { asm volatile("cp.async.wait_group 1;" ::: "memory"); }
__device__ __forceinline__ void cp_wait2()  { asm volatile("cp.async.wait_group 2;" ::: "memory"); }

__device__ __forceinline__ void ldsm_x4(uint32_t* r, uint32_t addr) {
    asm volatile("ldmatrix.sync.aligned.m8n8.x4.shared.b16 {%0,%1,%2,%3}, [%4];"
                 : "=r"(r[0]), "=r"(r[1]), "=r"(r[2]), "=r"(r[3]) : "r"(addr));
}

__device__ __forceinline__ void ldsm_x4_t(uint32_t* r, uint32_t addr) {
    asm volatile("ldmatrix.sync.aligned.m8n8.x4.trans.shared.b16 {%0,%1,%2,%3}, [%4];"
                 : "=r"(r[0]), "=r"(r[1]), "=r"(r[2]), "=r"(r[3]) : "r"(addr));
}

__device__ __forceinline__ void mma16816(float* d, const uint32_t* a, const uint32_t* b) {
    asm volatile(
        "mma.sync.aligned.m16n8k16.row.col.f32.f16.f16.f32 "
        "{%0,%1,%2,%3}, {%4,%5,%6,%7}, {%8,%9}, {%0,%1,%2,%3};"
        : "+f"(d[0]), "+f"(d[1]), "+f"(d[2]), "+f"(d[3])
        : "r"(a[0]), "r"(a[1]), "r"(a[2]), "r"(a[3]), "r"(b[0]), "r"(b[1]));
}

__device__ __forceinline__ uint32_t pack_h2(float a, float b) {
    __half2 t;
    t.x = __float2half(a);
    t.y = __float2half(b);
    return *(uint32_t*)&t;
}

// ===========================================================================
// Scratch (device globals)
// ===========================================================================
__device__ float g_h[(size_t)BQ_ * M_];

// Weights: fp16 hi/lo pairs, [N][K] k-major
#define WCAT_SZ ((size_t)L_ * 3072 * 1024)
#define WO_SZ   ((size_t)L_ * 1048576)
#define WFF_SZ  ((size_t)L_ * 4194304)
__device__ __align__(256) __half g_wqkvs_h[WCAT_SZ], g_wqkvs_l[WCAT_SZ];
__device__ __align__(256) __half g_wqkvc_h[WCAT_SZ], g_wqkvc_l[WCAT_SZ];
__device__ __align__(256) __half g_wos_h[WO_SZ], g_wos_l[WO_SZ];
__device__ __align__(256) __half g_woc_h[WO_SZ], g_woc_l[WO_SZ];
__device__ __align__(256) __half g_w1_h[WFF_SZ], g_w1_l[WFF_SZ];
__device__ __align__(256) __half g_w2_h[WFF_SZ], g_w2_l[WFF_SZ];

// Activations: SINGLE fp16 (A operands), except qkv which is a pair (flash precision)
__device__ __align__(256) __half g_nh  [(size_t)BQ_ * M_];
__device__ __align__(256) __half g_qkvh[(size_t)BQ_ * 3072], g_qkvl[(size_t)BQ_ * 3072];
__device__ __align__(256) __half g_ph  [(size_t)BQ_ * M_];
__device__ __align__(256) __half g_eh  [(size_t)B_ * T_ * M_];
__device__ __align__(256) __half g_sh  [(size_t)BQ_ * F_];

// mask bias: [B][Q][T] fp16 = max(tmask,qtmask) * (-30000)  (fp16-safe)
__device__ __align__(256) __half g_bias_s[(size_t)B_ * Q_ * T_];
__device__ __align__(256) __half g_bias_c[(size_t)B_ * Q_ * T_];

// ===========================================================================
// Block reductions (blockDim.x == 256)
// ===========================================================================
__device__ __forceinline__ float block_sum(float v) {
    __shared__ float sh[8];
    #pragma unroll
    for (int o = 16; o > 0; o >>= 1) v += __shfl_xor_sync(0xffffffffu, v, o);
    __syncthreads();
    if ((threadIdx.x & 31) == 0) sh[threadIdx.x >> 5] = v;
    __syncthreads();
    float t = 0.f;
    #pragma unroll
    for (int i = 0; i < 8; ++i) t += sh[i];
    return t;
}

// ===========================================================================
// Merged batched transpose + fp16 hi/lo split (weights, ONE launch).
// ===========================================================================
struct TSDesc {
    const float* src;
    __half *hi, *lo;
    int R, C, zs;
    long long s1, s2, s3;
    int tiles, cx, cy;
};
struct TSAll { TSDesc d[10]; };

__global__ void __launch_bounds__(256)
tsplit_all_k(TSAll a)
{
    __shared__ float t[32][33];
    int tix = blockIdx.x;
    int i = 0;
    while (tix >= a.d[i].tiles) { tix -= a.d[i].tiles; ++i; }
    const TSDesc& de = a.d[i];
    const int cxy = de.cx * de.cy;
    const int z = tix / cxy;
    const int rr = tix - z * cxy;
    const int by = rr / de.cx;
    const int bx = rr - by * de.cx;

    const long long sbase = (long long)z * de.R * de.C;
    const long long dbase = (long long)(z >> de.zs) * de.s1 +
                            (long long)(z & ((1 << de.zs) - 1)) * de.s2 + de.s3;
    const int c0 = bx << 5, r0 = by << 5;
    const int tx = threadIdx.x & 31, ty = threadIdx.x >> 5;
    #pragma unroll
    for (int k = 0; k < 4; ++k) {
        int r = r0 + ty + k * 8;
        t[ty + k * 8][tx] = de.src[sbase + (long long)r * de.C + c0 + tx];
    }
    __syncthreads();
    #pragma unroll
    for (int k = 0; k < 4; ++k) {
        int c = c0 + ty + k * 8;
        float v = t[tx][ty + k * 8];
        __half h = __float2half(v);
        long long o = dbase + (long long)c * de.R + r0 + tx;
        de.hi[o] = h;
        de.lo[o] = __float2half(v - __half2float(h));
    }
}

// ===========================================================================
// Elementwise single-fp16 convert (vectorized by 4)
// ===========================================================================
__global__ void __launch_bounds__(256)
tohalf_k(const float* __restrict__ x, __half* __restrict__ hi, int n4)
{
    int i = blockIdx.x * 256 + threadIdx.x;
    if (i >= n4) return;
    float4 v = ((const float4*)x)[i];
    __half h[4];
    h[0] = __float2half(v.x);
    h[1] = __float2half(v.y);
    h[2] = __float2half(v.z);
    h[3] = __float2half(v.w);
    *(uint2*)(hi + 4 * (size_t)i) = *(uint2*)h;
}

// ===========================================================================
// Mask bias build (BOTH arrays in one launch; blockIdx.z selects).
// ===========================================================================
__global__ void __launch_bounds__(256)
bias_all_k(const float* __restrict__ pmask, const float* __restrict__ qtself,
           const float* __restrict__ qtcross,
           __half* __restrict__ bs, __half* __restrict__ bc)
{
    const bool self = (blockIdx.z == 0);
    const float* tmask = self ? pmask : nullptr;
    const float* qtm   = self ? qtself : qtcross;
    __half* out = self ? bs : bc;
    const long long i2 = ((long long)blockIdx.x * 256 + threadIdx.x) * 2;
    const int t = (int)(i2 & 1023);
    const int b = (int)(i2 >> 20);
    float m0 = qtm[i2], m1 = qtm[i2 + 1];
    if (tmask) {
        m0 = fmaxf(m0, tmask[b * 1024 + t]);
        m1 = fmaxf(m1, tmask[b * 1024 + t + 1]);
    }
    const float c = -30000.0f;   // fp16-safe; exp underflows to exactly 0
    __half2 o;
    o.x = __float2half(m0 * c);
    o.y = __float2half(m1 * c);
    *(__half2*)(out + i2) = o;
}

// ===========================================================================
// Plain fp32 copy
// ===========================================================================
__global__ void __launch_bounds__(256)
copy_k(const float4* __restrict__ s, float4* __restrict__ d, int n4)
{
    int i = blockIdx.x * 256 + threadIdx.x;
    if (i < n4) d[i] = s[i];
}

// ===========================================================================
// LayerNorm over M=1024 -> single fp16. One block per row.
// ===========================================================================
__global__ void __launch_bounds__(256)
layernorm_h_k(const float* __restrict__ x, const float* __restrict__ g,
              const float* __restrict__ b, __half* __restrict__ hi)
{
    const int row = blockIdx.x;
    const float* xp = x + (size_t)row * M_;
    const int c = threadIdx.x << 2;
    float4 d = *(const float4*)(xp + c);
    float s  = d.x + d.y + d.z + d.w;
    float ss = d.x * d.x + d.y * d.y + d.z * d.z + d.w * d.w;
    s  = block_sum(s);
    ss = block_sum(ss);
    const float mean = s * (1.f / M_);
    const float var  = ss * (1.f / M_) - mean * mean;
    const float inv  = rsqrtf(var + 1e-5f);
    float4 g4 = *(const float4*)(g + c);
    float4 b4 = *(const float4*)(b + c);
    __half h[4];
    h[0] = __float2half((d.x - mean) * inv * g4.x + b4.x);
    h[1] = __float2half((d.y - mean) * inv * g4.y + b4.y);
    h[2] = __float2half((d.z - mean) * inv * g4.z + b4.z);
    h[3] = __float2half((d.w - mean) * inv * g4.w + b4.w);
    *(uint2*)(hi + (size_t)row * M_ + c) = *(uint2*)h;
}

// ===========================================================================
// Fused flash attention (fp16 hi/lo 3-product, fp32 softmax/accum).
// Output ph: SINGLE fp16 (A-operand of the wo GEMM).
// ===========================================================================
#define FL_QP  272
#define FL_SQH 0
#define FL_SQL 17408
#define FL_SKH 34816
#define FL_SKL 52224
#define FL_SVH 69632
#define FL_SVL 87040
#define FL_SMEM 104448

__global__ void __launch_bounds__(128)
flash_k(const __half* __restrict__ qkvh, const __half* __restrict__ qkvl,
        const __half* __restrict__ bias, __half* __restrict__ ph)
{
    extern __shared__ __align__(128) char smem[];
    const int tid = threadIdx.x, wid = tid >> 5, lane = tid & 31;
    const int bh = blockIdx.y, b = bh >> 3, h = bh & 7;
    const int q0 = blockIdx.x << 6;
    const uint32_t sb = smem_to_u32(smem);
    const int lr = lane >> 2, lq = lane & 3;
    const int qrow0 = b * 1024 + q0 + wid * 16 + lr;

    {
        int seg = tid;
        #pragma unroll
        for (int i = 0; i < 8; ++i, seg += 128) {
            int r = seg >> 4, s = seg & 15;
            uint32_t d = sb + FL_SQH + r * FL_QP + s * 16;
            long long g = (long long)(b * 1024 + q0 + r) * 3072 + h * 128 + s * 8;
            cp16(d, qkvh + g);
            cp16(d + (FL_SQL - FL_SQH), qkvl + g);
        }
        cp_commit(); cp_wait0();
    }
    __syncthreads();

    const uint32_t aoff  = ((lane & 7) + ((lane >> 3) & 1) * 8) * FL_QP + ((lane >> 4) & 1) * 16;
    const uint32_t boffK = ((lane & 7) + ((lane >> 4) & 1) * 8) * FL_QP + ((lane >> 3) & 1) * 16;

    uint32_t qfh[8][4], qfl[8][4];
    #pragma unroll
    for (int ks = 0; ks < 8; ++ks) {
        uint32_t ad = sb + FL_SQH + (wid * 16) * FL_QP + ks * 32 + aoff;
        ldsm_x4(qfh[ks], ad);
        ldsm_x4(qfl[ks], ad + (FL_SQL - FL_SQH));
    }

    float accO[16][4];
    #pragma unroll
    for (int i = 0; i < 16; ++i)
        #pragma unroll
        for (int j = 0; j < 4; ++j) accO[i][j] = 0.f;
    float mrow[2] = {-3.0e38f, -3.0e38f};
    float lrow[2] = {0.f, 0.f};
    const float inv = 0.08838834764831845f;
    const float L2E = 1.4426950408889634f;

    for (int tc = 0; tc < 16; ++tc) {
        const int t0 = tc << 6;

        uint32_t braw[16];
        int alive = 0;
        #pragma unroll
        for (int nf = 0; nf < 8; ++nf) {
            const int t = t0 + nf * 8 + lq * 2;
            #pragma unroll
            for (int i2 = 0; i2 < 2; ++i2) {
                uint32_t v = *(const uint32_t*)(bias + ((long long)(qrow0 + 8 * i2) << 10) + t);
                braw[nf * 2 + i2] = v;
                __half2 bb = *(__half2*)&v;
                if (__half2float(bb.x) > -1.0e4f || __half2float(bb.y) > -1.0e4f)
                    alive = 1;
            }
        }
        if (!__syncthreads_or(alive)) continue;

        int seg = tid;
        #pragma unroll
        for (int i = 0; i < 8; ++i, seg += 128) {
            int r = seg >> 4, s = seg & 15;
            long long g = (long long)(b * 1024 + t0 + r) * 3072 + h * 128 + s * 8;
            uint32_t d = sb + FL_SKH + r * FL_QP + s * 16;
            cp16(d, qkvh + g + 1024);
            cp16(d + (FL_SKL - FL_SKH), qkvl + g + 1024);
            uint32_t dv = sb + FL_SVH + r * FL_QP + s * 16;
            cp16(dv, qkvh + g + 2048);
            cp16(dv + (FL_SVL - FL_SVH), qkvl + g + 2048);
        }
        cp_commit(); cp_wait0();
        __syncthreads();

        float accS[8][4];
        #pragma unroll
        for (int i = 0; i < 8; ++i)
            #pragma unroll
            for (int j = 0; j < 4; ++j) accS[i][j] = 0.f;
        #pragma unroll
        for (int ks = 0; ks < 8; ++ks) {
            #pragma unroll
            for (int nt = 0; nt < 4; ++nt) {
                uint32_t bh4[4], bl4[4];
                uint32_t bd = sb + FL_SKH + (nt * 16) * FL_QP + ks * 32 + boffK;
                ldsm_x4(bh4, bd);
                ldsm_x4(bl4, bd + (FL_SKL - FL_SKH));
                mma16816(accS[2 * nt],     qfh[ks], &bh4[0]);
                mma16816(accS[2 * nt + 1], qfh[ks], &bh4[2]);
                mma16816(accS[2 * nt],     qfh[ks], &bl4[0]);
                mma16816(accS[2 * nt + 1], qfh[ks], &bl4[2]);
                mma16816(accS[2 * nt],     qfl[ks], &bh4[0]);
                mma16816(accS[2 * nt + 1], qfl[ks], &bh4[2]);
            }
        }

        float pm[2] = {-3.0e38f, -3.0e38f};
        #pragma unroll
        for (int nf = 0; nf < 8; ++nf) {
            #pragma unroll
            for (int i2 = 0; i2 < 2; ++i2) {
                __half2 bb = *(__half2*)&braw[nf * 2 + i2];
                float s0 = accS[nf][i2 * 2 + 0] * inv + __half2float(bb.x);
                float s1 = accS[nf][i2 * 2 + 1] * inv + __half2float(bb.y);
                accS[nf][i2 * 2 + 0] = s0;
                accS[nf][i2 * 2 + 1] = s1;
                pm[i2] = fmaxf(pm[i2], fmaxf(s0, s1));
            }
        }
        #pragma unroll
        for (int i2 = 0; i2 < 2; ++i2) {
            pm[i2] = fmaxf(pm[i2], __shfl_xor_sync(0xffffffffu, pm[i2], 1));
            pm[i2] = fmaxf(pm[i2], __shfl_xor_sync(0xffffffffu, pm[i2], 2));
            float mnew = fmaxf(mrow[i2], pm[i2]);
            float sc = exp2f((mrow[i2] - mnew) * L2E);
            mrow[i2] = mnew;
            lrow[i2] *= sc;
            #pragma unroll
            for (int nf = 0; nf < 16; ++nf) {
                accO[nf][i2 * 2 + 0] *= sc;
                accO[nf][i2 * 2 + 1] *= sc;
            }
        }
        float psum[2] = {0.f, 0.f};
        #pragma unroll
        for (int nf = 0; nf < 8; ++nf) {
            #pragma unroll
            for (int i2 = 0; i2 < 2; ++i2) {
                float p0 = exp2f((accS[nf][i2 * 2 + 0] - mrow[i2]) * L2E);
                float p1 = exp2f((accS[nf][i2 * 2 + 1] - mrow[i2]) * L2E);
                accS[nf][i2 * 2 + 0] = p0;
                accS[nf][i2 * 2 + 1] = p1;
                psum[i2] += p0 + p1;
            }
        }
        #pragma unroll
        for (int i2 = 0; i2 < 2; ++i2) {
            psum[i2] += __shfl_xor_sync(0xffffffffu, psum[i2], 1);
            psum[i2] += __shfl_xor_sync(0xffffffffu, psum[i2], 2);
            lrow[i2] += psum[i2];
        }

        #pragma unroll
        for (int kk = 0; kk < 4; ++kk) {
            uint32_t pah[4], pal[4];
            #pragma unroll
            for (int hv = 0; hv < 2; ++hv) {
                const float v0 = accS[2 * kk + hv][0], v1 = accS[2 * kk + hv][1];
                const float v2 = accS[2 * kk + hv][2], v3 = accS[2 * kk + hv][3];
                pah[0 + hv * 2] = pack_h2(v0, v1);
                pah[1 + hv * 2] = pack_h2(v2, v3);
                __half2 h01 = *(__half2*)&pah[0 + hv * 2];
                __half2 h23 = *(__half2*)&pah[1 + hv * 2];
                pal[0 + hv * 2] = pack_h2(v0 - __half2float(h01.x),
                                          v1 - __half2float(h01.y));
                pal[1 + hv * 2] = pack_h2(v2 - __half2float(h23.x),
                                          v3 - __half2float(h23.y));
            }
            #pragma unroll
            for (int np = 0; np < 8; ++np) {
                uint32_t vh4[4], vl4[4];
                uint32_t bd = sb + FL_SVH + (kk * 16) * FL_QP + np * 32 + aoff;
                ldsm_x4_t(vh4, bd);
                ldsm_x4_t(vl4, bd + (FL_SVL - FL_SVH));
                mma16816(accO[2 * np],     pah, &vh4[0]);
                mma16816(accO[2 * np + 1], pah, &vh4[2]);
                mma16816(accO[2 * np],     pah, &vl4[0]);
                mma16816(accO[2 * np + 1], pah, &vl4[2]);
                mma16816(accO[2 * np],     pal, &vh4[0]);
                mma16816(accO[2 * np + 1], pal, &vh4[2]);
            }
        }
        __syncthreads();
    }

    float rp[2];
    rp[0] = 1.f / lrow[0];
    rp[1] = 1.f / lrow[1];
    #pragma unroll
    for (int nf = 0; nf < 16; ++nf) {
        #pragma unroll
        for (int i2 = 0; i2 < 2; ++i2) {
            float v0 = accO[nf][i2 * 2 + 0] * rp[i2];
            float v1 = accO[nf][i2 * 2 + 1] * rp[i2];
            long long o = ((long long)(qrow0 + 8 * i2) << 10) + h * 128 + nf * 8 + lq * 2;
            __half2 hh;
            hh.x = __float2half(v0);
            hh.y = __float2half(v1);
            *(__half2*)(ph + o) = hh;
        }
    }
}

// ===========================================================================
// fp16 2-product GEMM (dense): C[M x N] = A[M x K] * (Bh + Bl)[N x K]^T
// A single fp16 activation; B fp16 hi/lo weight pair.
// CTA tile 128x128, BK=16, 8 warps, 4-stage cp.async, 2 CTAs/SM.
// Stage: [A 6KB][Bh 6KB][Bl 6KB] = 18KB; 4 stages = 72KB.
// EPI: 0 none | 1 resid+rowmask | 2 bias+relu | 3 bias+resid+rowmask
// OUT: 0 fp32 | 1 fp16 hi/lo pair | 2 fp16 single
// ===========================================================================
#define PITCH_B 48
#define TILE_B  (128 * PITCH_B)    // 6144
#define STAGE_B (3 * TILE_B)       // 18432
#define MG_SMEM (4 * STAGE_B)      // 73728

__device__ __forceinline__ void mg_load(
    uint32_t sb, const __half* __restrict__ A,
    const __half* __restrict__ Bh, const __half* __restrict__ Bl,
    int tid, int m0, int n0, int lda, int ldb, int koff)
{
    const int r = tid >> 1, s = tid & 1;
    const uint32_t dA = sb + r * PITCH_B + s * 16;
    cp16(dA, A + (long long)(m0 + r) * lda + koff + s * 8);
    const uint32_t dB = sb + TILE_B + r * PITCH_B + s * 16;
    const long long gB = (long long)(n0 + r) * ldb + koff + s * 8;
    cp16(dB,          Bh + gB);
    cp16(dB + TILE_B, Bl + gB);
    cp_commit();
}

template <int EPI, int OUT>
__global__ void __launch_bounds__(256, 2)
mgemm_k(const __half* __restrict__ A, int lda,
        const __half* __restrict__ Bh, const __half* __restrict__ Bl, int ldb,
        float* Cf, __half* Ch, __half* Cl, int ldc,
        const float* __restrict__ resid, int ldr,
        const float* __restrict__ bias,
        const float* __restrict__ rowmask, int Kdim)
{
    extern __shared__ __align__(128) char smem[];
    const int tid = threadIdx.x, wid = tid >> 5, lane = tid & 31;
    const int m0 = blockIdx.y << 7, n0 = blockIdx.x << 7;
    const int wm = (wid >> 1) << 5;
    const int wn = (wid & 1) << 6;
    const uint32_t sb0 = smem_to_u32(smem);

    const uint32_t aoff = ((lane & 7) + ((lane >> 3) & 1) * 8) * PITCH_B + ((lane >> 4) & 1) * 16;
    const uint32_t boff = ((lane & 7) + ((lane >> 4) & 1) * 8) * PITCH_B + ((lane >> 3) & 1) * 16;

    float acc[2][8][4];
    #pragma unroll
    for (int i = 0; i < 2; ++i)
        #pragma unroll
        for (int j = 0; j < 8; ++j)
            #pragma unroll
            for (int k = 0; k < 4; ++k) acc[i][j][k] = 0.f;

    const int NC = Kdim >> 4;
    mg_load(sb0,               A, Bh, Bl, tid, m0, n0, lda, ldb, 0);
    mg_load(sb0 + STAGE_B,     A, Bh, Bl, tid, m0, n0, lda, ldb, 16);
    mg_load(sb0 + 2 * STAGE_B, A, Bh, Bl, tid, m0, n0, lda, ldb, 32);

    for (int kt = 0; kt < NC; ++kt) {
        if (kt + 2 < NC)      cp_wait2();
        else if (kt + 1 < NC) cp_wait1();
        else                  cp_wait0();
        __syncthreads();
        if (kt + 3 < NC)
            mg_load(sb0 + (uint32_t)((kt + 3) & 3) * STAGE_B,
                    A, Bh, Bl, tid, m0, n0, lda, ldb, (kt + 3) << 4);

        const uint32_t sA = sb0 + (uint32_t)(kt & 3) * STAGE_B;
        const uint32_t sB = sA + TILE_B;

        uint32_t a[2][4];
        #pragma unroll
        for (int mf = 0; mf < 2; ++mf)
            ldsm_x4(a[mf], sA + (wm + mf * 16) * PITCH_B + aoff);
        #pragma unroll
        for (int np = 0; np < 4; ++np) {
            uint32_t b_hi[4], b_lo[4];
            uint32_t bd = sB + (wn + np * 16) * PITCH_B + boff;
            ldsm_x4(b_hi, bd);
            ldsm_x4(b_lo, bd + TILE_B);
            #pragma unroll
            for (int mf = 0; mf < 2; ++mf) {
                mma16816(acc[mf][2 * np],     a[mf], &b_hi[0]);
                mma16816(acc[mf][2 * np + 1], a[mf], &b_hi[2]);
                mma16816(acc[mf][2 * np],     a[mf], &b_lo[0]);
                mma16816(acc[mf][2 * np + 1], a[mf], &b_lo[2]);
            }
        }
    }

    const int lr = lane >> 2, lc2 = (lane & 3) << 1;
    #pragma unroll
    for (int mf = 0; mf < 2; ++mf) {
        #pragma unroll
        for (int h2 = 0; h2 < 2; ++h2) {
            const long long r = m0 + wm + mf * 16 + h2 * 8 + lr;
            float mfac = 1.f;
            if (EPI == 1 || EPI == 3) mfac = 1.f - rowmask[r];
            #pragma unroll
            for (int nf = 0; nf < 8; ++nf) {
                float v0 = acc[mf][nf][h2 * 2 + 0];
                float v1 = acc[mf][nf][h2 * 2 + 1];
                const long long c = n0 + wn + nf * 8 + lc2;
                if (EPI >= 2) { v0 += bias[c]; v1 += bias[c + 1]; }
                if (EPI == 2) { v0 = fmaxf(v0, 0.f); v1 = fmaxf(v1, 0.f); }
                if (EPI == 1 || EPI == 3) {
                    float2 rs = *(const float2*)(resid + r * ldr + c);
                    v0 = rs.x + v0 * mfac;
                    v1 = rs.y + v1 * mfac;
                }
                if (OUT == 0) {
                    float2 o; o.x = v0; o.y = v1;
                    *(float2*)(Cf + r * ldc + c) = o;
                } else if (OUT == 1) {
                    __half h0 = __float2half(v0), h1 = __float2half(v1);
                    __half2 hh, ll;
                    hh.x = h0; hh.y = h1;
                    ll.x = __float2half(v0 - __half2float(h0));
                    ll.y = __float2half(v1 - __half2float(h1));
                    *(__half2*)(Ch + r * ldc + c) = hh;
                    *(__half2*)(Cl + r * ldc + c) = ll;
                } else {
                    __half2 hh;
                    hh.x = __float2half(v0);
                    hh.y = __float2half(v1);
                    *(__half2*)(Ch + r * ldc + c) = hh;
                }
            }
        }
    }
}

// ===========================================================================
// Host orchestration
// ===========================================================================
extern "C" void kernel_launch(void* const* d_in, const int* in_sizes, int n_in,
                              void* d_out, int out_size)
{
    (void)in_sizes; (void)n_in; (void)out_size;

    const float* enc_out = (const float*)d_in[0];
    const float* x       = (const float*)d_in[1];
    const float* pmask   = (const float*)d_in[2];
    const float* qtself  = (const float*)d_in[3];
    const float* qtcross = (const float*)d_in[4];
    const float* swq = (const float*)d_in[5];
    const float* swk = (const float*)d_in[6];
    const float* swv = (const float*)d_in[7];
    const float* swo = (const float*)d_in[8];
    const float* cwq = (const float*)d_in[9];
    const float* cwk = (const float*)d_in[10];
    const float* cwv = (const float*)d_in[11];
    const float* cwo = (const float*)d_in[12];
    const float* w1  = (const float*)d_in[13];
    const float* b1  = (const float*)d_in[14];
    const float* w2  = (const float*)d_in[15];
    const float* b2  = (const float*)d_in[16];
    const float* ln1g = (const float*)d_in[17];
    const float* ln1b = (const float*)d_in[18];
    const float* ln2g = (const float*)d_in[19];
    const float* ln2b = (const float*)d_in[20];
    const float* ln3g = (const float*)d_in[21];
    const float* ln3b = (const float*)d_in[22];

    float* hb;
    cudaGetSymbolAddress((void**)&hb, g_h);

    __half *wqkvs_h, *wqkvs_l, *wqkvc_h, *wqkvc_l;
    __half *wos_h, *wos_l, *woc_h, *woc_l, *w1h, *w1l, *w2h, *w2l;
    __half *nh, *qkvh, *qkvl, *ph, *eh, *sh, *bs, *bc;
    cudaGetSymbolAddress((void**)&wqkvs_h, g_wqkvs_h);
    cudaGetSymbolAddress((void**)&wqkvs_l, g_wqkvs_l);
    cudaGetSymbolAddress((void**)&wqkvc_h, g_wqkvc_h);
    cudaGetSymbolAddress((void**)&wqkvc_l, g_wqkvc_l);
    cudaGetSymbolAddress((void**)&wos_h, g_wos_h); cudaGetSymbolAddress((void**)&wos_l, g_wos_l);
    cudaGetSymbolAddress((void**)&woc_h, g_woc_h); cudaGetSymbolAddress((void**)&woc_l, g_woc_l);
    cudaGetSymbolAddress((void**)&w1h, g_w1_h);    cudaGetSymbolAddress((void**)&w1l, g_w1_l);
    cudaGetSymbolAddress((void**)&w2h, g_w2_h);    cudaGetSymbolAddress((void**)&w2l, g_w2_l);
    cudaGetSymbolAddress((void**)&nh, g_nh);
    cudaGetSymbolAddress((void**)&qkvh, g_qkvh); cudaGetSymbolAddress((void**)&qkvl, g_qkvl);
    cudaGetSymbolAddress((void**)&ph, g_ph);
    cudaGetSymbolAddress((void**)&eh, g_eh);
    cudaGetSymbolAddress((void**)&sh, g_sh);
    cudaGetSymbolAddress((void**)&bs, g_bias_s); cudaGetSymbolAddress((void**)&bc, g_bias_c);

    cudaFuncSetAttribute(mgemm_k<0,1>, cudaFuncAttributeMaxDynamicSharedMemorySize, MG_SMEM);
    cudaFuncSetAttribute(mgemm_k<1,0>, cudaFuncAttributeMaxDynamicSharedMemorySize, MG_SMEM);
    cudaFuncSetAttribute(mgemm_k<2,2>, cudaFuncAttributeMaxDynamicSharedMemorySize, MG_SMEM);
    cudaFuncSetAttribute(mgemm_k<3,0>, cudaFuncAttributeMaxDynamicSharedMemorySize, MG_SMEM);
    cudaFuncSetAttribute(flash_k, cudaFuncAttributeMaxDynamicSharedMemorySize, FL_SMEM);

    // --- launch 1: h = x ---
    copy_k<<<BQ_ * M_ / 4 / 256, 256>>>((const float4*)x, (float4*)hb, BQ_ * M_ / 4);
    // --- launch 2: all weight transposes+splits ---
    {
        const long long sL = 3145728LL;
        const long long sH = 131072LL;
        TSAll a;
        auto set = [&](int i, const float* src, __half* hi, __half* lo,
                       int R, int C, int zs, long long s1, long long s2, long long s3, int Z) {
            a.d[i] = { src, hi, lo, R, C, zs, s1, s2, s3, (C / 32) * (R / 32) * Z,
                       C / 32, R / 32 };
        };
        set(0, swq, wqkvs_h, wqkvs_l, M_, K_, 3, sL, sH, 0LL,        L_ * H_);
        set(1, swk, wqkvs_h, wqkvs_l, M_, K_, 3, sL, sH, 1048576LL,  L_ * H_);
        set(2, swv, wqkvs_h, wqkvs_l, M_, K_, 3, sL, sH, 2097152LL,  L_ * H_);
        set(3, cwq, wqkvc_h, wqkvc_l, M_, K_, 3, sL, sH, 0LL,        L_ * H_);
        set(4, cwk, wqkvc_h, wqkvc_l, M_, K_, 3, sL, sH, 1048576LL,  L_ * H_);
        set(5, cwv, wqkvc_h, wqkvc_l, M_, K_, 3, sL, sH, 2097152LL,  L_ * H_);
        set(6, swo, wos_h, wos_l, H_ * V_, M_, 0, 1048576LL, 0LL, 0LL, L_);
        set(7, cwo, woc_h, woc_l, H_ * V_, M_, 0, 1048576LL, 0LL, 0LL, L_);
        set(8, w1,  w1h, w1l, M_, F_, 0, 4194304LL, 0LL, 0LL, L_);
        set(9, w2,  w2h, w2l, F_, M_, 0, 4194304LL, 0LL, 0LL, L_);
        int total = 0;
        for (int i = 0; i < 10; ++i) total += a.d[i].tiles;
        tsplit_all_k<<<total, 256>>>(a);
    }

    const dim3 gQKV(3072 / 128, BQ_ / 128);
    const dim3 gPq (M_ / 128,  BQ_ / 128);
    const dim3 gKV (2048 / 128, BQ_ / 128);
    const dim3 gP  (M_ / 128,  BQ_ / 128);
    const dim3 gF1 (F_ / 128,  BQ_ / 128);
    const dim3 gFL (Q_ / 64, B_ * H_);
    const long long wS  = 3145728LL;
    const size_t wO  = 1048576;
    const size_t wLF = 4194304;

    for (int l = 0; l < L_; ++l) {
        for (int pass = 0; pass < 2; ++pass) {
            const bool self = (pass == 0);
            const float* lng = self ? ln1g : ln2g;
            const float* lnb = self ? ln1b : ln2b;
            __half* wcat_h = (self ? wqkvs_h : wqkvc_h) + l * wS;
            __half* wcat_l = (self ? wqkvs_l : wqkvc_l) + l * wS;
            __half* wo_h = (self ? wos_h : woc_h) + l * wO;
            __half* wo_l = (self ? wos_l : woc_l) + l * wO;

            // l=0 self: LN is launch #3, QKV mgemm is #4 <- ncu target
            layernorm_h_k<<<BQ_, 256>>>(hb, lng + l * M_, lnb + l * M_, nh);
            if (self) {
                mgemm_k<0,1><<<gQKV, 256, MG_SMEM>>>(nh, M_, wcat_h, wcat_l, M_,
                                                     nullptr, qkvh, qkvl, 3072,
                                                     nullptr, 0, nullptr, nullptr, M_);
            } else {
                mgemm_k<0,1><<<gPq, 256, MG_SMEM>>>(nh, M_, wcat_h, wcat_l, M_,
                                                    nullptr, qkvh, qkvl, 3072,
                                                    nullptr, 0, nullptr, nullptr, M_);
                mgemm_k<0,1><<<gKV, 256, MG_SMEM>>>(eh, M_,
                                                    wcat_h + 1048576, wcat_l + 1048576, M_,
                                                    nullptr, qkvh + 1024, qkvl + 1024, 3072,
                                                    nullptr, 0, nullptr, nullptr, M_);
            }
            // deferred prep (first iteration only)
            if (l == 0 && self) {
                dim3 gb(B_ * Q_ * T_ / 2 / 256, 1, 2);
                bias_all_k<<<gb, 256>>>(pmask, qtself, qtcross, bs, bc);
                tohalf_k<<<B_ * T_ * M_ / 4 / 256, 256>>>(enc_out, eh, B_ * T_ * M_ / 4);
            }
            flash_k<<<gFL, 128, FL_SMEM>>>(qkvh, qkvl, self ? bs : bc, ph);
            mgemm_k<1,0><<<gP, 256, MG_SMEM>>>(ph, M_, wo_h, wo_l, M_,
                                               hb, nullptr, nullptr, M_,
                                               hb, M_, nullptr, pmask, M_);
        }

        // ---- FFN ----
        layernorm_h_k<<<BQ_, 256>>>(hb, ln3g + l * M_, ln3b + l * M_, nh);
        mgemm_k<2,2><<<gF1, 256, MG_SMEM>>>(nh, M_, w1h + l * wLF, w1l + l * wLF, M_,
                                            nullptr, sh, nullptr, F_,
                                            nullptr, 0, b1 + l * F_, nullptr, M_);
        float* cdst = (l == L_ - 1) ? (float*)d_out : hb;
        mgemm_k<3,0><<<gP, 256, MG_SMEM>>>(sh, F_, w2h + l * wLF, w2l + l * wLF, F_,
                                           cdst, nullptr, nullptr, M_,
                                           hb, M_, b2 + l * M_, pmask, F_);
    }
}

// round 13
// speedup vs baseline: 2.0039x; 1.4940x over previous
#include <cuda_runtime.h>
#include <cuda_fp16.h>
#include <cstdint>
#include <cstddef>

// Problem constants
#define L_  6
#define H_  8
#define M_  1024
#define K_  128
#define V_  128
#define F_  4096
#define B_  4
#define Q_  1024
#define T_  1024
#define BQ_ 4096   // B_*Q_

// ===========================================================================
// Low-level helpers (base PTX only)
// ===========================================================================
__device__ __forceinline__ uint32_t smem_to_u32(const void* p) {
    uint32_t a;
    asm("{ .reg .u64 t; cvta.to.shared.u64 t, %1; cvt.u32.u64 %0, t; }"
        : "=r"(a) : "l"(p));
    return a;
}

__device__ __forceinline__ void cp16(uint32_t dst, const void* src) {
    asm volatile("cp.async.cg.shared.global [%0], [%1], 16;"
                 :: "r"(dst), "l"(__cvta_generic_to_global(src)));
}
__device__ __forceinline__ void cp_commit() { asm volatile("cp.async.commit_group;" ::: "memory"); }
__device__ __forceinline__ void cp_wait0()  { asm volatile("cp.async.wait_group 0;" ::: "memory"); }
__device__ __forceinline__ void cp_wait1()  { asm volatile("cp.async.wait_group 1;" ::: "memory"); }
__device__ __forceinline__ void cp_wait2()  { asm volatile("cp.async.wait_group 2;" ::: "memory"); }

__device__ __forceinline__ void ldsm_x4(uint32_t* r, uint32_t addr) {
    asm volatile("ldmatrix.sync.aligned.m8n8.x4.shared.b16 {%0,%1,%2,%3}, [%4];"
                 : "=r"(r[0]), "=r"(r[1]), "=r"(r[2]), "=r"(r[3]) : "r"(addr));
}

__device__ __forceinline__ void ldsm_x4_t(uint32_t* r, uint32_t addr) {
    asm volatile("ldmatrix.sync.aligned.m8n8.x4.trans.shared.b16 {%0,%1,%2,%3}, [%4];"
                 : "=r"(r[0]), "=r"(r[1]), "=r"(r[2]), "=r"(r[3]) : "r"(addr));
}

__device__ __forceinline__ void mma16816(float* d, const uint32_t* a, const uint32_t* b) {
    asm volatile(
        "mma.sync.aligned.m16n8k16.row.col.f32.f16.f16.f32 "
        "{%0,%1,%2,%3}, {%4,%5,%6,%7}, {%8,%9}, {%0,%1,%2,%3};"
        : "+f"(d[0]), "+f"(d[1]), "+f"(d[2]), "+f"(d[3])
        : "r"(a[0]), "r"(a[1]), "r"(a[2]), "r"(a[3]), "r"(b[0]), "r"(b[1]));
}

__device__ __forceinline__ uint32_t pack_h2(float a, float b) {
    __half2 t;
    t.x = __float2half(a);
    t.y = __float2half(b);
    return *(uint32_t*)&t;
}

// ===========================================================================
// Scratch (device globals)
// ===========================================================================
__device__ float g_h[(size_t)BQ_ * M_];

// Weights: SINGLE fp16, [N][K] k-major
#define WCAT_SZ ((size_t)L_ * 3072 * 1024)
#define WO_SZ   ((size_t)L_ * 1048576)
#define WFF_SZ  ((size_t)L_ * 4194304)
__device__ __align__(256) __half g_wqkvs[WCAT_SZ];
__device__ __align__(256) __half g_wqkvc[WCAT_SZ];
__device__ __align__(256) __half g_wos[WO_SZ];
__device__ __align__(256) __half g_woc[WO_SZ];
__device__ __align__(256) __half g_w1[WFF_SZ];
__device__ __align__(256) __half g_w2[WFF_SZ];

// Activations: SINGLE fp16 (A operands); qkv is a hi/lo pair (flash precision)
__device__ __align__(256) __half g_nh  [(size_t)BQ_ * M_];
__device__ __align__(256) __half g_qkvh[(size_t)BQ_ * 3072], g_qkvl[(size_t)BQ_ * 3072];
__device__ __align__(256) __half g_ph  [(size_t)BQ_ * M_];
__device__ __align__(256) __half g_eh  [(size_t)B_ * T_ * M_];
__device__ __align__(256) __half g_sh  [(size_t)BQ_ * F_];

// mask bias: [B][Q][T] fp16 = max(tmask,qtmask) * (-30000)
__device__ __align__(256) __half g_bias_s[(size_t)B_ * Q_ * T_];
__device__ __align__(256) __half g_bias_c[(size_t)B_ * Q_ * T_];

// ===========================================================================
// Block reductions (blockDim.x == 256)
// ===========================================================================
__device__ __forceinline__ float block_sum(float v) {
    __shared__ float sh[8];
    #pragma unroll
    for (int o = 16; o > 0; o >>= 1) v += __shfl_xor_sync(0xffffffffu, v, o);
    __syncthreads();
    if ((threadIdx.x & 31) == 0) sh[threadIdx.x >> 5] = v;
    __syncthreads();
    float t = 0.f;
    #pragma unroll
    for (int i = 0; i < 8; ++i) t += sh[i];
    return t;
}

// ===========================================================================
// Merged batched transpose + fp16 convert (weights, ONE launch).
// ===========================================================================
struct TSDesc {
    const float* src;
    __half* hi;
    int R, C, zs;
    long long s1, s2, s3;
    int tiles, cx, cy;
};
struct TSAll { TSDesc d[10]; };

__global__ void __launch_bounds__(256)
tsplit_all_k(TSAll a)
{
    __shared__ float t[32][33];
    int tix = blockIdx.x;
    int i = 0;
    while (tix >= a.d[i].tiles) { tix -= a.d[i].tiles; ++i; }
    const TSDesc& de = a.d[i];
    const int cxy = de.cx * de.cy;
    const int z = tix / cxy;
    const int rr = tix - z * cxy;
    const int by = rr / de.cx;
    const int bx = rr - by * de.cx;

    const long long sbase = (long long)z * de.R * de.C;
    const long long dbase = (long long)(z >> de.zs) * de.s1 +
                            (long long)(z & ((1 << de.zs) - 1)) * de.s2 + de.s3;
    const int c0 = bx << 5, r0 = by << 5;
    const int tx = threadIdx.x & 31, ty = threadIdx.x >> 5;
    #pragma unroll
    for (int k = 0; k < 4; ++k) {
        int r = r0 + ty + k * 8;
        t[ty + k * 8][tx] = de.src[sbase + (long long)r * de.C + c0 + tx];
    }
    __syncthreads();
    #pragma unroll
    for (int k = 0; k < 4; ++k) {
        int c = c0 + ty + k * 8;
        de.hi[dbase + (long long)c * de.R + r0 + tx] = __float2half(t[tx][ty + k * 8]);
    }
}

// ===========================================================================
// Elementwise single-fp16 convert (vectorized by 4)
// ===========================================================================
__global__ void __launch_bounds__(256)
tohalf_k(const float* __restrict__ x, __half* __restrict__ hi, int n4)
{
    int i = blockIdx.x * 256 + threadIdx.x;
    if (i >= n4) return;
    float4 v = ((const float4*)x)[i];
    __half h[4];
    h[0] = __float2half(v.x);
    h[1] = __float2half(v.y);
    h[2] = __float2half(v.z);
    h[3] = __float2half(v.w);
    *(uint2*)(hi + 4 * (size_t)i) = *(uint2*)h;
}

// ===========================================================================
// Mask bias build (BOTH arrays in one launch; blockIdx.z selects).
// ===========================================================================
__global__ void __launch_bounds__(256)
bias_all_k(const float* __restrict__ pmask, const float* __restrict__ qtself,
           const float* __restrict__ qtcross,
           __half* __restrict__ bs, __half* __restrict__ bc)
{
    const bool self = (blockIdx.z == 0);
    const float* tmask = self ? pmask : nullptr;
    const float* qtm   = self ? qtself : qtcross;
    __half* out = self ? bs : bc;
    const long long i2 = ((long long)blockIdx.x * 256 + threadIdx.x) * 2;
    const int t = (int)(i2 & 1023);
    const int b = (int)(i2 >> 20);
    float m0 = qtm[i2], m1 = qtm[i2 + 1];
    if (tmask) {
        m0 = fmaxf(m0, tmask[b * 1024 + t]);
        m1 = fmaxf(m1, tmask[b * 1024 + t + 1]);
    }
    const float c = -30000.0f;
    __half2 o;
    o.x = __float2half(m0 * c);
    o.y = __float2half(m1 * c);
    *(__half2*)(out + i2) = o;
}

// ===========================================================================
// Plain fp32 copy
// ===========================================================================
__global__ void __launch_bounds__(256)
copy_k(const float4* __restrict__ s, float4* __restrict__ d, int n4)
{
    int i = blockIdx.x * 256 + threadIdx.x;
    if (i < n4) d[i] = s[i];
}

// ===========================================================================
// LayerNorm over M=1024 -> single fp16. One block per row.
// ===========================================================================
__global__ void __launch_bounds__(256)
layernorm_h_k(const float* __restrict__ x, const float* __restrict__ g,
              const float* __restrict__ b, __half* __restrict__ hi)
{
    const int row = blockIdx.x;
    const float* xp = x + (size_t)row * M_;
    const int c = threadIdx.x << 2;
    float4 d = *(const float4*)(xp + c);
    float s  = d.x + d.y + d.z + d.w;
    float ss = d.x * d.x + d.y * d.y + d.z * d.z + d.w * d.w;
    s  = block_sum(s);
    ss = block_sum(ss);
    const float mean = s * (1.f / M_);
    const float var  = ss * (1.f / M_) - mean * mean;
    const float inv  = rsqrtf(var + 1e-5f);
    float4 g4 = *(const float4*)(g + c);
    float4 b4 = *(const float4*)(b + c);
    __half h[4];
    h[0] = __float2half((d.x - mean) * inv * g4.x + b4.x);
    h[1] = __float2half((d.y - mean) * inv * g4.y + b4.y);
    h[2] = __float2half((d.z - mean) * inv * g4.z + b4.z);
    h[3] = __float2half((d.w - mean) * inv * g4.w + b4.w);
    *(uint2*)(hi + (size_t)row * M_ + c) = *(uint2*)h;
}

// ===========================================================================
// Fused flash attention (fp16 hi/lo 3-product, fp32 softmax/accum).
// Unchanged from R12 (passing, rel_err contribution negligible).
// ===========================================================================
#define FL_QP  272
#define FL_SQH 0
#define FL_SQL 17408
#define FL_SKH 34816
#define FL_SKL 52224
#define FL_SVH 69632
#define FL_SVL 87040
#define FL_SMEM 104448

__global__ void __launch_bounds__(128)
flash_k(const __half* __restrict__ qkvh, const __half* __restrict__ qkvl,
        const __half* __restrict__ bias, __half* __restrict__ ph)
{
    extern __shared__ __align__(128) char smem[];
    const int tid = threadIdx.x, wid = tid >> 5, lane = tid & 31;
    const int bh = blockIdx.y, b = bh >> 3, h = bh & 7;
    const int q0 = blockIdx.x << 6;
    const uint32_t sb = smem_to_u32(smem);
    const int lr = lane >> 2, lq = lane & 3;
    const int qrow0 = b * 1024 + q0 + wid * 16 + lr;

    {
        int seg = tid;
        #pragma unroll
        for (int i = 0; i < 8; ++i, seg += 128) {
            int r = seg >> 4, s = seg & 15;
            uint32_t d = sb + FL_SQH + r * FL_QP + s * 16;
            long long g = (long long)(b * 1024 + q0 + r) * 3072 + h * 128 + s * 8;
            cp16(d, qkvh + g);
            cp16(d + (FL_SQL - FL_SQH), qkvl + g);
        }
        cp_commit(); cp_wait0();
    }
    __syncthreads();

    const uint32_t aoff  = ((lane & 7) + ((lane >> 3) & 1) * 8) * FL_QP + ((lane >> 4) & 1) * 16;
    const uint32_t boffK = ((lane & 7) + ((lane >> 4) & 1) * 8) * FL_QP + ((lane >> 3) & 1) * 16;

    uint32_t qfh[8][4], qfl[8][4];
    #pragma unroll
    for (int ks = 0; ks < 8; ++ks) {
        uint32_t ad = sb + FL_SQH + (wid * 16) * FL_QP + ks * 32 + aoff;
        ldsm_x4(qfh[ks], ad);
        ldsm_x4(qfl[ks], ad + (FL_SQL - FL_SQH));
    }

    float accO[16][4];
    #pragma unroll
    for (int i = 0; i < 16; ++i)
        #pragma unroll
        for (int j = 0; j < 4; ++j) accO[i][j] = 0.f;
    float mrow[2] = {-3.0e38f, -3.0e38f};
    float lrow[2] = {0.f, 0.f};
    const float inv = 0.08838834764831845f;
    const float L2E = 1.4426950408889634f;

    for (int tc = 0; tc < 16; ++tc) {
        const int t0 = tc << 6;

        uint32_t braw[16];
        int alive = 0;
        #pragma unroll
        for (int nf = 0; nf < 8; ++nf) {
            const int t = t0 + nf * 8 + lq * 2;
            #pragma unroll
            for (int i2 = 0; i2 < 2; ++i2) {
                uint32_t v = *(const uint32_t*)(bias + ((long long)(qrow0 + 8 * i2) << 10) + t);
                braw[nf * 2 + i2] = v;
                __half2 bb = *(__half2*)&v;
                if (__half2float(bb.x) > -1.0e4f || __half2float(bb.y) > -1.0e4f)
                    alive = 1;
            }
        }
        if (!__syncthreads_or(alive)) continue;

        int seg = tid;
        #pragma unroll
        for (int i = 0; i < 8; ++i, seg += 128) {
            int r = seg >> 4, s = seg & 15;
            long long g = (long long)(b * 1024 + t0 + r) * 3072 + h * 128 + s * 8;
            uint32_t d = sb + FL_SKH + r * FL_QP + s * 16;
            cp16(d, qkvh + g + 1024);
            cp16(d + (FL_SKL - FL_SKH), qkvl + g + 1024);
            uint32_t dv = sb + FL_SVH + r * FL_QP + s * 16;
            cp16(dv, qkvh + g + 2048);
            cp16(dv + (FL_SVL - FL_SVH), qkvl + g + 2048);
        }
        cp_commit(); cp_wait0();
        __syncthreads();

        float accS[8][4];
        #pragma unroll
        for (int i = 0; i < 8; ++i)
            #pragma unroll
            for (int j = 0; j < 4; ++j) accS[i][j] = 0.f;
        #pragma unroll
        for (int ks = 0; ks < 8; ++ks) {
            #pragma unroll
            for (int nt = 0; nt < 4; ++nt) {
                uint32_t bh4[4], bl4[4];
                uint32_t bd = sb + FL_SKH + (nt * 16) * FL_QP + ks * 32 + boffK;
                ldsm_x4(bh4, bd);
                ldsm_x4(bl4, bd + (FL_SKL - FL_SKH));
                mma16816(accS[2 * nt],     qfh[ks], &bh4[0]);
                mma16816(accS[2 * nt + 1], qfh[ks], &bh4[2]);
                mma16816(accS[2 * nt],     qfh[ks], &bl4[0]);
                mma16816(accS[2 * nt + 1], qfh[ks], &bl4[2]);
                mma16816(accS[2 * nt],     qfl[ks], &bh4[0]);
                mma16816(accS[2 * nt + 1], qfl[ks], &bh4[2]);
            }
        }

        float pm[2] = {-3.0e38f, -3.0e38f};
        #pragma unroll
        for (int nf = 0; nf < 8; ++nf) {
            #pragma unroll
            for (int i2 = 0; i2 < 2; ++i2) {
                __half2 bb = *(__half2*)&braw[nf * 2 + i2];
                float s0 = accS[nf][i2 * 2 + 0] * inv + __half2float(bb.x);
                float s1 = accS[nf][i2 * 2 + 1] * inv + __half2float(bb.y);
                accS[nf][i2 * 2 + 0] = s0;
                accS[nf][i2 * 2 + 1] = s1;
                pm[i2] = fmaxf(pm[i2], fmaxf(s0, s1));
            }
        }
        #pragma unroll
        for (int i2 = 0; i2 < 2; ++i2) {
            pm[i2] = fmaxf(pm[i2], __shfl_xor_sync(0xffffffffu, pm[i2], 1));
            pm[i2] = fmaxf(pm[i2], __shfl_xor_sync(0xffffffffu, pm[i2], 2));
            float mnew = fmaxf(mrow[i2], pm[i2]);
            float sc = exp2f((mrow[i2] - mnew) * L2E);
            mrow[i2] = mnew;
            lrow[i2] *= sc;
            #pragma unroll
            for (int nf = 0; nf < 16; ++nf) {
                accO[nf][i2 * 2 + 0] *= sc;
                accO[nf][i2 * 2 + 1] *= sc;
            }
        }
        float psum[2] = {0.f, 0.f};
        #pragma unroll
        for (int nf = 0; nf < 8; ++nf) {
            #pragma unroll
            for (int i2 = 0; i2 < 2; ++i2) {
                float p0 = exp2f((accS[nf][i2 * 2 + 0] - mrow[i2]) * L2E);
                float p1 = exp2f((accS[nf][i2 * 2 + 1] - mrow[i2]) * L2E);
                accS[nf][i2 * 2 + 0] = p0;
                accS[nf][i2 * 2 + 1] = p1;
                psum[i2] += p0 + p1;
            }
        }
        #pragma unroll
        for (int i2 = 0; i2 < 2; ++i2) {
            psum[i2] += __shfl_xor_sync(0xffffffffu, psum[i2], 1);
            psum[i2] += __shfl_xor_sync(0xffffffffu, psum[i2], 2);
            lrow[i2] += psum[i2];
        }

        #pragma unroll
        for (int kk = 0; kk < 4; ++kk) {
            uint32_t pah[4], pal[4];
            #pragma unroll
            for (int hv = 0; hv < 2; ++hv) {
                const float v0 = accS[2 * kk + hv][0], v1 = accS[2 * kk + hv][1];
                const float v2 = accS[2 * kk + hv][2], v3 = accS[2 * kk + hv][3];
                pah[0 + hv * 2] = pack_h2(v0, v1);
                pah[1 + hv * 2] = pack_h2(v2, v3);
                __half2 h01 = *(__half2*)&pah[0 + hv * 2];
                __half2 h23 = *(__half2*)&pah[1 + hv * 2];
                pal[0 + hv * 2] = pack_h2(v0 - __half2float(h01.x),
                                          v1 - __half2float(h01.y));
                pal[1 + hv * 2] = pack_h2(v2 - __half2float(h23.x),
                                          v3 - __half2float(h23.y));
            }
            #pragma unroll
            for (int np = 0; np < 8; ++np) {
                uint32_t vh4[4], vl4[4];
                uint32_t bd = sb + FL_SVH + (kk * 16) * FL_QP + np * 32 + aoff;
                ldsm_x4_t(vh4, bd);
                ldsm_x4_t(vl4, bd + (FL_SVL - FL_SVH));
                mma16816(accO[2 * np],     pah, &vh4[0]);
                mma16816(accO[2 * np + 1], pah, &vh4[2]);
                mma16816(accO[2 * np],     pah, &vl4[0]);
                mma16816(accO[2 * np + 1], pah, &vl4[2]);
                mma16816(accO[2 * np],     pal, &vh4[0]);
                mma16816(accO[2 * np + 1], pal, &vh4[2]);
            }
        }
        __syncthreads();
    }

    float rp[2];
    rp[0] = 1.f / lrow[0];
    rp[1] = 1.f / lrow[1];
    #pragma unroll
    for (int nf = 0; nf < 16; ++nf) {
        #pragma unroll
        for (int i2 = 0; i2 < 2; ++i2) {
            float v0 = accO[nf][i2 * 2 + 0] * rp[i2];
            float v1 = accO[nf][i2 * 2 + 1] * rp[i2];
            long long o = ((long long)(qrow0 + 8 * i2) << 10) + h * 128 + nf * 8 + lq * 2;
            __half2 hh;
            hh.x = __float2half(v0);
            hh.y = __float2half(v1);
            *(__half2*)(ph + o) = hh;
        }
    }
}

// ===========================================================================
// fp16 1-product GEMM (dense): C[M x N] = A[M x K] * B[N x K]^T
// A and B both single fp16. CTA 128x128, BK=16, 8 warps, 4-stage cp.async.
// Stage: [A 6KB][B 6KB] = 12KB; 4 stages = 48KB; 2 CTAs/SM.
// EPI: 0 none | 1 resid+rowmask | 2 bias+relu | 3 bias+resid+rowmask
// OUT: 0 fp32 | 1 fp16 hi/lo pair | 2 fp16 single
// ===========================================================================
#define PITCH_B 48
#define TILE_B  (128 * PITCH_B)    // 6144
#define STAGE_B (2 * TILE_B)       // 12288
#define MG_SMEM (4 * STAGE_B)      // 49152

__device__ __forceinline__ void mg_load(
    uint32_t sb, const __half* __restrict__ A, const __half* __restrict__ Bw,
    int tid, int m0, int n0, int lda, int ldb, int koff)
{
    const int r = tid >> 1, s = tid & 1;
    cp16(sb + r * PITCH_B + s * 16,
         A + (long long)(m0 + r) * lda + koff + s * 8);
    cp16(sb + TILE_B + r * PITCH_B + s * 16,
         Bw + (long long)(n0 + r) * ldb + koff + s * 8);
    cp_commit();
}

template <int EPI, int OUT>
__global__ void __launch_bounds__(256, 2)
mgemm_k(const __half* __restrict__ A, int lda,
        const __half* __restrict__ Bw, int ldb,
        float* Cf, __half* Ch, __half* Cl, int ldc,
        const float* __restrict__ resid, int ldr,
        const float* __restrict__ bias,
        const float* __restrict__ rowmask, int Kdim)
{
    extern __shared__ __align__(128) char smem[];
    const int tid = threadIdx.x, wid = tid >> 5, lane = tid & 31;
    const int m0 = blockIdx.y << 7, n0 = blockIdx.x << 7;
    const int wm = (wid >> 1) << 5;
    const int wn = (wid & 1) << 6;
    const uint32_t sb0 = smem_to_u32(smem);

    const uint32_t aoff = ((lane & 7) + ((lane >> 3) & 1) * 8) * PITCH_B + ((lane >> 4) & 1) * 16;
    const uint32_t boff = ((lane & 7) + ((lane >> 4) & 1) * 8) * PITCH_B + ((lane >> 3) & 1) * 16;

    float acc[2][8][4];
    #pragma unroll
    for (int i = 0; i < 2; ++i)
        #pragma unroll
        for (int j = 0; j < 8; ++j)
            #pragma unroll
            for (int k = 0; k < 4; ++k) acc[i][j][k] = 0.f;

    const int NC = Kdim >> 4;
    mg_load(sb0,               A, Bw, tid, m0, n0, lda, ldb, 0);
    mg_load(sb0 + STAGE_B,     A, Bw, tid, m0, n0, lda, ldb, 16);
    mg_load(sb0 + 2 * STAGE_B, A, Bw, tid, m0, n0, lda, ldb, 32);

    for (int kt = 0; kt < NC; ++kt) {
        if (kt + 2 < NC)      cp_wait2();
        else if (kt + 1 < NC) cp_wait1();
        else                  cp_wait0();
        __syncthreads();
        if (kt + 3 < NC)
            mg_load(sb0 + (uint32_t)((kt + 3) & 3) * STAGE_B,
                    A, Bw, tid, m0, n0, lda, ldb, (kt + 3) << 4);

        const uint32_t sA = sb0 + (uint32_t)(kt & 3) * STAGE_B;
        const uint32_t sB = sA + TILE_B;

        uint32_t a[2][4];
        #pragma unroll
        for (int mf = 0; mf < 2; ++mf)
            ldsm_x4(a[mf], sA + (wm + mf * 16) * PITCH_B + aoff);
        #pragma unroll
        for (int np = 0; np < 4; ++np) {
            uint32_t b4[4];
            ldsm_x4(b4, sB + (wn + np * 16) * PITCH_B + boff);
            #pragma unroll
            for (int mf = 0; mf < 2; ++mf) {
                mma16816(acc[mf][2 * np],     a[mf], &b4[0]);
                mma16816(acc[mf][2 * np + 1], a[mf], &b4[2]);
            }
        }
    }

    const int lr = lane >> 2, lc2 = (lane & 3) << 1;
    #pragma unroll
    for (int mf = 0; mf < 2; ++mf) {
        #pragma unroll
        for (int h2 = 0; h2 < 2; ++h2) {
            const long long r = m0 + wm + mf * 16 + h2 * 8 + lr;
            float mfac = 1.f;
            if (EPI == 1 || EPI == 3) mfac = 1.f - rowmask[r];
            #pragma unroll
            for (int nf = 0; nf < 8; ++nf) {
                float v0 = acc[mf][nf][h2 * 2 + 0];
                float v1 = acc[mf][nf][h2 * 2 + 1];
                const long long c = n0 + wn + nf * 8 + lc2;
                if (EPI >= 2) { v0 += bias[c]; v1 += bias[c + 1]; }
                if (EPI == 2) { v0 = fmaxf(v0, 0.f); v1 = fmaxf(v1, 0.f); }
                if (EPI == 1 || EPI == 3) {
                    float2 rs = *(const float2*)(resid + r * ldr + c);
                    v0 = rs.x + v0 * mfac;
                    v1 = rs.y + v1 * mfac;
                }
                if (OUT == 0) {
                    float2 o; o.x = v0; o.y = v1;
                    *(float2*)(Cf + r * ldc + c) = o;
                } else if (OUT == 1) {
                    __half h0 = __float2half(v0), h1 = __float2half(v1);
                    __half2 hh, ll;
                    hh.x = h0; hh.y = h1;
                    ll.x = __float2half(v0 - __half2float(h0));
                    ll.y = __float2half(v1 - __half2float(h1));
                    *(__half2*)(Ch + r * ldc + c) = hh;
                    *(__half2*)(Cl + r * ldc + c) = ll;
                } else {
                    __half2 hh;
                    hh.x = __float2half(v0);
                    hh.y = __float2half(v1);
                    *(__half2*)(Ch + r * ldc + c) = hh;
                }
            }
        }
    }
}

// ===========================================================================
// Host orchestration
// ===========================================================================
extern "C" void kernel_launch(void* const* d_in, const int* in_sizes, int n_in,
                              void* d_out, int out_size)
{
    (void)in_sizes; (void)n_in; (void)out_size;

    const float* enc_out = (const float*)d_in[0];
    const float* x       = (const float*)d_in[1];
    const float* pmask   = (const float*)d_in[2];
    const float* qtself  = (const float*)d_in[3];
    const float* qtcross = (const float*)d_in[4];
    const float* swq = (const float*)d_in[5];
    const float* swk = (const float*)d_in[6];
    const float* swv = (const float*)d_in[7];
    const float* swo = (const float*)d_in[8];
    const float* cwq = (const float*)d_in[9];
    const float* cwk = (const float*)d_in[10];
    const float* cwv = (const float*)d_in[11];
    const float* cwo = (const float*)d_in[12];
    const float* w1  = (const float*)d_in[13];
    const float* b1  = (const float*)d_in[14];
    const float* w2  = (const float*)d_in[15];
    const float* b2  = (const float*)d_in[16];
    const float* ln1g = (const float*)d_in[17];
    const float* ln1b = (const float*)d_in[18];
    const float* ln2g = (const float*)d_in[19];
    const float* ln2b = (const float*)d_in[20];
    const float* ln3g = (const float*)d_in[21];
    const float* ln3b = (const float*)d_in[22];

    float* hb;
    cudaGetSymbolAddress((void**)&hb, g_h);

    __half *wqkvs, *wqkvc, *wos, *woc, *w1p, *w2p;
    __half *nh, *qkvh, *qkvl, *ph, *eh, *sh, *bs, *bc;
    cudaGetSymbolAddress((void**)&wqkvs, g_wqkvs);
    cudaGetSymbolAddress((void**)&wqkvc, g_wqkvc);
    cudaGetSymbolAddress((void**)&wos, g_wos);
    cudaGetSymbolAddress((void**)&woc, g_woc);
    cudaGetSymbolAddress((void**)&w1p, g_w1);
    cudaGetSymbolAddress((void**)&w2p, g_w2);
    cudaGetSymbolAddress((void**)&nh, g_nh);
    cudaGetSymbolAddress((void**)&qkvh, g_qkvh); cudaGetSymbolAddress((void**)&qkvl, g_qkvl);
    cudaGetSymbolAddress((void**)&ph, g_ph);
    cudaGetSymbolAddress((void**)&eh, g_eh);
    cudaGetSymbolAddress((void**)&sh, g_sh);
    cudaGetSymbolAddress((void**)&bs, g_bias_s); cudaGetSymbolAddress((void**)&bc, g_bias_c);

    cudaFuncSetAttribute(mgemm_k<0,1>, cudaFuncAttributeMaxDynamicSharedMemorySize, MG_SMEM);
    cudaFuncSetAttribute(mgemm_k<1,0>, cudaFuncAttributeMaxDynamicSharedMemorySize, MG_SMEM);
    cudaFuncSetAttribute(mgemm_k<2,2>, cudaFuncAttributeMaxDynamicSharedMemorySize, MG_SMEM);
    cudaFuncSetAttribute(mgemm_k<3,0>, cudaFuncAttributeMaxDynamicSharedMemorySize, MG_SMEM);
    cudaFuncSetAttribute(flash_k, cudaFuncAttributeMaxDynamicSharedMemorySize, FL_SMEM);

    // --- launch 1: h = x ---
    copy_k<<<BQ_ * M_ / 4 / 256, 256>>>((const float4*)x, (float4*)hb, BQ_ * M_ / 4);
    // --- launch 2: all weight transposes+converts ---
    {
        const long long sL = 3145728LL;
        const long long sH = 131072LL;
        TSAll a;
        auto set = [&](int i, const float* src, __half* hi,
                       int R, int C, int zs, long long s1, long long s2, long long s3, int Z) {
            a.d[i] = { src, hi, R, C, zs, s1, s2, s3, (C / 32) * (R / 32) * Z,
                       C / 32, R / 32 };
        };
        set(0, swq, wqkvs, M_, K_, 3, sL, sH, 0LL,        L_ * H_);
        set(1, swk, wqkvs, M_, K_, 3, sL, sH, 1048576LL,  L_ * H_);
        set(2, swv, wqkvs, M_, K_, 3, sL, sH, 2097152LL,  L_ * H_);
        set(3, cwq, wqkvc, M_, K_, 3, sL, sH, 0LL,        L_ * H_);
        set(4, cwk, wqkvc, M_, K_, 3, sL, sH, 1048576LL,  L_ * H_);
        set(5, cwv, wqkvc, M_, K_, 3, sL, sH, 2097152LL,  L_ * H_);
        set(6, swo, wos, H_ * V_, M_, 0, 1048576LL, 0LL, 0LL, L_);
        set(7, cwo, woc, H_ * V_, M_, 0, 1048576LL, 0LL, 0LL, L_);
        set(8, w1,  w1p, M_, F_, 0, 4194304LL, 0LL, 0LL, L_);
        set(9, w2,  w2p, F_, M_, 0, 4194304LL, 0LL, 0LL, L_);
        int total = 0;
        for (int i = 0; i < 10; ++i) total += a.d[i].tiles;
        tsplit_all_k<<<total, 256>>>(a);
    }

    const dim3 gQKV(3072 / 128, BQ_ / 128);
    const dim3 gPq (M_ / 128,  BQ_ / 128);
    const dim3 gKV (2048 / 128, BQ_ / 128);
    const dim3 gP  (M_ / 128,  BQ_ / 128);
    const dim3 gF1 (F_ / 128,  BQ_ / 128);
    const dim3 gFL (Q_ / 64, B_ * H_);
    const long long wS  = 3145728LL;
    const size_t wO  = 1048576;
    const size_t wLF = 4194304;

    for (int l = 0; l < L_; ++l) {
        for (int pass = 0; pass < 2; ++pass) {
            const bool self = (pass == 0);
            const float* lng = self ? ln1g : ln2g;
            const float* lnb = self ? ln1b : ln2b;
            __half* wcat = (self ? wqkvs : wqkvc) + l * wS;
            __half* wo_p = (self ? wos : woc) + l * wO;

            // l=0 self: LN is launch #3, QKV mgemm is #4 <- ncu target
            layernorm_h_k<<<BQ_, 256>>>(hb, lng + l * M_, lnb + l * M_, nh);
            if (self) {
                mgemm_k<0,1><<<gQKV, 256, MG_SMEM>>>(nh, M_, wcat, M_,
                                                     nullptr, qkvh, qkvl, 3072,
                                                     nullptr, 0, nullptr, nullptr, M_);
            } else {
                mgemm_k<0,1><<<gPq, 256, MG_SMEM>>>(nh, M_, wcat, M_,
                                                    nullptr, qkvh, qkvl, 3072,
                                                    nullptr, 0, nullptr, nullptr, M_);
                mgemm_k<0,1><<<gKV, 256, MG_SMEM>>>(eh, M_, wcat + 1048576, M_,
                                                    nullptr, qkvh + 1024, qkvl + 1024, 3072,
                                                    nullptr, 0, nullptr, nullptr, M_);
            }
            // deferred prep (first iteration only)
            if (l == 0 && self) {
                dim3 gb(B_ * Q_ * T_ / 2 / 256, 1, 2);
                bias_all_k<<<gb, 256>>>(pmask, qtself, qtcross, bs, bc);
                tohalf_k<<<B_ * T_ * M_ / 4 / 256, 256>>>(enc_out, eh, B_ * T_ * M_ / 4);
            }
            flash_k<<<gFL, 128, FL_SMEM>>>(qkvh, qkvl, self ? bs : bc, ph);
            mgemm_k<1,0><<<gP, 256, MG_SMEM>>>(ph, M_, wo_p, M_,
                                               hb, nullptr, nullptr, M_,
                                               hb, M_, nullptr, pmask, M_);
        }

        // ---- FFN ----
        layernorm_h_k<<<BQ_, 256>>>(hb, ln3g + l * M_, ln3b + l * M_, nh);
        mgemm_k<2,2><<<gF1, 256, MG_SMEM>>>(nh, M_, w1p + l * wLF, M_,
                                            nullptr, sh, nullptr, F_,
                                            nullptr, 0, b1 + l * F_, nullptr, M_);
        float* cdst = (l == L_ - 1) ? (float*)d_out : hb;
        mgemm_k<3,0><<<gP, 256, MG_SMEM>>>(sh, F_, w2p + l * wLF, F_,
                                           cdst, nullptr, nullptr, M_,
                                           hb, M_, b2 + l * M_, pmask, F_);
    }
}

// round 15
// speedup vs baseline: 2.0673x; 1.0316x over previous
#include <cuda_runtime.h>
#include <cuda_fp16.h>
#include <cstdint>
#include <cstddef>

// Problem constants
#define L_  6
#define H_  8
#define M_  1024
#define K_  128
#define V_  128
#define F_  4096
#define B_  4
#define Q_  1024
#define T_  1024
#define BQ_ 4096   // B_*Q_

// ===========================================================================
// Low-level helpers (base PTX only)
// ===========================================================================
__device__ __forceinline__ uint32_t smem_to_u32(const void* p) {
    uint32_t a;
    asm("{ .reg .u64 t; cvta.to.shared.u64 t, %1; cvt.u32.u64 %0, t; }"
        : "=r"(a) : "l"(p));
    return a;
}

__device__ __forceinline__ void cp16(uint32_t dst, const void* src) {
    asm volatile("cp.async.cg.shared.global [%0], [%1], 16;"
                 :: "r"(dst), "l"(__cvta_generic_to_global(src)));
}
__device__ __forceinline__ void cp_commit() { asm volatile("cp.async.commit_group;" ::: "memory"); }
__device__ __forceinline__ void cp_wait0()  { asm volatile("cp.async.wait_group 0;" ::: "memory"); }
__device__ __forceinline__ void cp_wait1()  { asm volatile("cp.async.wait_group 1;" ::: "memory"); }
__device__ __forceinline__ void cp_wait2()  { asm volatile("cp.async.wait_group 2;" ::: "memory"); }

__device__ __forceinline__ void ldsm_x4(uint32_t* r, uint32_t addr) {
    asm volatile("ldmatrix.sync.aligned.m8n8.x4.shared.b16 {%0,%1,%2,%3}, [%4];"
                 : "=r"(r[0]), "=r"(r[1]), "=r"(r[2]), "=r"(r[3]) : "r"(addr));
}

__device__ __forceinline__ void ldsm_x4_t(uint32_t* r, uint32_t addr) {
    asm volatile("ldmatrix.sync.aligned.m8n8.x4.trans.shared.b16 {%0,%1,%2,%3}, [%4];"
                 : "=r"(r[0]), "=r"(r[1]), "=r"(r[2]), "=r"(r[3]) : "r"(addr));
}

__device__ __forceinline__ void mma16816(float* d, const uint32_t* a, const uint32_t* b) {
    asm volatile(
        "mma.sync.aligned.m16n8k16.row.col.f32.f16.f16.f32 "
        "{%0,%1,%2,%3}, {%4,%5,%6,%7}, {%8,%9}, {%0,%1,%2,%3};"
        : "+f"(d[0]), "+f"(d[1]), "+f"(d[2]), "+f"(d[3])
        : "r"(a[0]), "r"(a[1]), "r"(a[2]), "r"(a[3]), "r"(b[0]), "r"(b[1]));
}

__device__ __forceinline__ uint32_t pack_h2(float a, float b) {
    __half2 t;
    t.x = __float2half(a);
    t.y = __float2half(b);
    return *(uint32_t*)&t;
}

// ===========================================================================
// Scratch (device globals)
// ===========================================================================
__device__ float g_h[(size_t)BQ_ * M_];

// Weights: SINGLE fp16, [N][K] k-major
#define WCAT_SZ ((size_t)L_ * 3072 * 1024)
#define WO_SZ   ((size_t)L_ * 1048576)
#define WFF_SZ  ((size_t)L_ * 4194304)
__device__ __align__(256) __half g_wqkvs[WCAT_SZ];
__device__ __align__(256) __half g_wqkvc[WCAT_SZ];
__device__ __align__(256) __half g_wos[WO_SZ];
__device__ __align__(256) __half g_woc[WO_SZ];
__device__ __align__(256) __half g_w1[WFF_SZ];
__device__ __align__(256) __half g_w2[WFF_SZ];

// Activations: SINGLE fp16 (A operands); qkv is a hi/lo pair (flash precision)
__device__ __align__(256) __half g_nh  [(size_t)BQ_ * M_];
__device__ __align__(256) __half g_qkvh[(size_t)BQ_ * 3072], g_qkvl[(size_t)BQ_ * 3072];
__device__ __align__(256) __half g_ph  [(size_t)BQ_ * M_];
__device__ __align__(256) __half g_eh  [(size_t)B_ * T_ * M_];
__device__ __align__(256) __half g_sh  [(size_t)BQ_ * F_];

// mask bias: [B][Q][T] fp16 = max(tmask,qtmask) * (-30000)
__device__ __align__(256) __half g_bias_s[(size_t)B_ * Q_ * T_];
__device__ __align__(256) __half g_bias_c[(size_t)B_ * Q_ * T_];

// ===========================================================================
// Block reductions (blockDim.x == 256)
// ===========================================================================
__device__ __forceinline__ float block_sum(float v) {
    __shared__ float sh[8];
    #pragma unroll
    for (int o = 16; o > 0; o >>= 1) v += __shfl_xor_sync(0xffffffffu, v, o);
    __syncthreads();
    if ((threadIdx.x & 31) == 0) sh[threadIdx.x >> 5] = v;
    __syncthreads();
    float t = 0.f;
    #pragma unroll
    for (int i = 0; i < 8; ++i) t += sh[i];
    return t;
}

// ===========================================================================
// Merged batched transpose + fp16 convert (weights, ONE launch).
// ===========================================================================
struct TSDesc {
    const float* src;
    __half* hi;
    int R, C, zs;
    long long s1, s2, s3;
    int tiles, cx, cy;
};
struct TSAll { TSDesc d[10]; };

__global__ void __launch_bounds__(256)
tsplit_all_k(TSAll a)
{
    __shared__ float t[32][33];
    int tix = blockIdx.x;
    int i = 0;
    while (tix >= a.d[i].tiles) { tix -= a.d[i].tiles; ++i; }
    const TSDesc& de = a.d[i];
    const int cxy = de.cx * de.cy;
    const int z = tix / cxy;
    const int rr = tix - z * cxy;
    const int by = rr / de.cx;
    const int bx = rr - by * de.cx;

    const long long sbase = (long long)z * de.R * de.C;
    const long long dbase = (long long)(z >> de.zs) * de.s1 +
                            (long long)(z & ((1 << de.zs) - 1)) * de.s2 + de.s3;
    const int c0 = bx << 5, r0 = by << 5;
    const int tx = threadIdx.x & 31, ty = threadIdx.x >> 5;
    #pragma unroll
    for (int k = 0; k < 4; ++k) {
        int r = r0 + ty + k * 8;
        t[ty + k * 8][tx] = de.src[sbase + (long long)r * de.C + c0 + tx];
    }
    __syncthreads();
    #pragma unroll
    for (int k = 0; k < 4; ++k) {
        int c = c0 + ty + k * 8;
        de.hi[dbase + (long long)c * de.R + r0 + tx] = __float2half(t[tx][ty + k * 8]);
    }
}

// ===========================================================================
// Elementwise single-fp16 convert (vectorized by 4)
// ===========================================================================
__global__ void __launch_bounds__(256)
tohalf_k(const float* __restrict__ x, __half* __restrict__ hi, int n4)
{
    int i = blockIdx.x * 256 + threadIdx.x;
    if (i >= n4) return;
    float4 v = ((const float4*)x)[i];
    __half h[4];
    h[0] = __float2half(v.x);
    h[1] = __float2half(v.y);
    h[2] = __float2half(v.z);
    h[3] = __float2half(v.w);
    *(uint2*)(hi + 4 * (size_t)i) = *(uint2*)h;
}

// ===========================================================================
// Mask bias build (BOTH arrays in one launch; blockIdx.z selects).
// ===========================================================================
__global__ void __launch_bounds__(256)
bias_all_k(const float* __restrict__ pmask, const float* __restrict__ qtself,
           const float* __restrict__ qtcross,
           __half* __restrict__ bs, __half* __restrict__ bc)
{
    const bool self = (blockIdx.z == 0);
    const float* tmask = self ? pmask : nullptr;
    const float* qtm   = self ? qtself : qtcross;
    __half* out = self ? bs : bc;
    const long long i2 = ((long long)blockIdx.x * 256 + threadIdx.x) * 2;
    const int t = (int)(i2 & 1023);
    const int b = (int)(i2 >> 20);
    float m0 = qtm[i2], m1 = qtm[i2 + 1];
    if (tmask) {
        m0 = fmaxf(m0, tmask[b * 1024 + t]);
        m1 = fmaxf(m1, tmask[b * 1024 + t + 1]);
    }
    const float c = -30000.0f;
    __half2 o;
    o.x = __float2half(m0 * c);
    o.y = __float2half(m1 * c);
    *(__half2*)(out + i2) = o;
}

// ===========================================================================
// Plain fp32 copy
// ===========================================================================
__global__ void __launch_bounds__(256)
copy_k(const float4* __restrict__ s, float4* __restrict__ d, int n4)
{
    int i = blockIdx.x * 256 + threadIdx.x;
    if (i < n4) d[i] = s[i];
}

// ===========================================================================
// LayerNorm over M=1024 -> single fp16. One block per row.
// ===========================================================================
__global__ void __launch_bounds__(256)
layernorm_h_k(const float* __restrict__ x, const float* __restrict__ g,
              const float* __restrict__ b, __half* __restrict__ hi)
{
    const int row = blockIdx.x;
    const float* xp = x + (size_t)row * M_;
    const int c = threadIdx.x << 2;
    float4 d = *(const float4*)(xp + c);
    float s  = d.x + d.y + d.z + d.w;
    float ss = d.x * d.x + d.y * d.y + d.z * d.z + d.w * d.w;
    s  = block_sum(s);
    ss = block_sum(ss);
    const float mean = s * (1.f / M_);
    const float var  = ss * (1.f / M_) - mean * mean;
    const float inv  = rsqrtf(var + 1e-5f);
    float4 g4 = *(const float4*)(g + c);
    float4 b4 = *(const float4*)(b + c);
    __half h[4];
    h[0] = __float2half((d.x - mean) * inv * g4.x + b4.x);
    h[1] = __float2half((d.y - mean) * inv * g4.y + b4.y);
    h[2] = __float2half((d.z - mean) * inv * g4.z + b4.z);
    h[3] = __float2half((d.w - mean) * inv * g4.w + b4.w);
    *(uint2*)(hi + (size_t)row * M_ + c) = *(uint2*)h;
}

// ===========================================================================
// Fused flash attention (fp16 hi/lo 3-product, fp32 softmax/accum).
// Unchanged from R13 (passing).
// ===========================================================================
#define FL_QP  272
#define FL_SQH 0
#define FL_SQL 17408
#define FL_SKH 34816
#define FL_SKL 52224
#define FL_SVH 69632
#define FL_SVL 87040
#define FL_SMEM 104448

__global__ void __launch_bounds__(128)
flash_k(const __half* __restrict__ qkvh, const __half* __restrict__ qkvl,
        const __half* __restrict__ bias, __half* __restrict__ ph)
{
    extern __shared__ __align__(128) char smem[];
    const int tid = threadIdx.x, wid = tid >> 5, lane = tid & 31;
    const int bh = blockIdx.y, b = bh >> 3, h = bh & 7;
    const int q0 = blockIdx.x << 6;
    const uint32_t sb = smem_to_u32(smem);
    const int lr = lane >> 2, lq = lane & 3;
    const int qrow0 = b * 1024 + q0 + wid * 16 + lr;

    {
        int seg = tid;
        #pragma unroll
        for (int i = 0; i < 8; ++i, seg += 128) {
            int r = seg >> 4, s = seg & 15;
            uint32_t d = sb + FL_SQH + r * FL_QP + s * 16;
            long long g = (long long)(b * 1024 + q0 + r) * 3072 + h * 128 + s * 8;
            cp16(d, qkvh + g);
            cp16(d + (FL_SQL - FL_SQH), qkvl + g);
        }
        cp_commit(); cp_wait0();
    }
    __syncthreads();

    const uint32_t aoff  = ((lane & 7) + ((lane >> 3) & 1) * 8) * FL_QP + ((lane >> 4) & 1) * 16;
    const uint32_t boffK = ((lane & 7) + ((lane >> 4) & 1) * 8) * FL_QP + ((lane >> 3) & 1) * 16;

    uint32_t qfh[8][4], qfl[8][4];
    #pragma unroll
    for (int ks = 0; ks < 8; ++ks) {
        uint32_t ad = sb + FL_SQH + (wid * 16) * FL_QP + ks * 32 + aoff;
        ldsm_x4(qfh[ks], ad);
        ldsm_x4(qfl[ks], ad + (FL_SQL - FL_SQH));
    }

    float accO[16][4];
    #pragma unroll
    for (int i = 0; i < 16; ++i)
        #pragma unroll
        for (int j = 0; j < 4; ++j) accO[i][j] = 0.f;
    float mrow[2] = {-3.0e38f, -3.0e38f};
    float lrow[2] = {0.f, 0.f};
    const float inv = 0.08838834764831845f;
    const float L2E = 1.4426950408889634f;

    for (int tc = 0; tc < 16; ++tc) {
        const int t0 = tc << 6;

        uint32_t braw[16];
        int alive = 0;
        #pragma unroll
        for (int nf = 0; nf < 8; ++nf) {
            const int t = t0 + nf * 8 + lq * 2;
            #pragma unroll
            for (int i2 = 0; i2 < 2; ++i2) {
                uint32_t v = *(const uint32_t*)(bias + ((long long)(qrow0 + 8 * i2) << 10) + t);
                braw[nf * 2 + i2] = v;
                __half2 bb = *(__half2*)&v;
                if (__half2float(bb.x) > -1.0e4f || __half2float(bb.y) > -1.0e4f)
                    alive = 1;
            }
        }
        if (!__syncthreads_or(alive)) continue;

        int seg = tid;
        #pragma unroll
        for (int i = 0; i < 8; ++i, seg += 128) {
            int r = seg >> 4, s = seg & 15;
            long long g = (long long)(b * 1024 + t0 + r) * 3072 + h * 128 + s * 8;
            uint32_t d = sb + FL_SKH + r * FL_QP + s * 16;
            cp16(d, qkvh + g + 1024);
            cp16(d + (FL_SKL - FL_SKH), qkvl + g + 1024);
            uint32_t dv = sb + FL_SVH + r * FL_QP + s * 16;
            cp16(dv, qkvh + g + 2048);
            cp16(dv + (FL_SVL - FL_SVH), qkvl + g + 2048);
        }
        cp_commit(); cp_wait0();
        __syncthreads();

        float accS[8][4];
        #pragma unroll
        for (int i = 0; i < 8; ++i)
            #pragma unroll
            for (int j = 0; j < 4; ++j) accS[i][j] = 0.f;
        #pragma unroll
        for (int ks = 0; ks < 8; ++ks) {
            #pragma unroll
            for (int nt = 0; nt < 4; ++nt) {
                uint32_t bh4[4], bl4[4];
                uint32_t bd = sb + FL_SKH + (nt * 16) * FL_QP + ks * 32 + boffK;
                ldsm_x4(bh4, bd);
                ldsm_x4(bl4, bd + (FL_SKL - FL_SKH));
                mma16816(accS[2 * nt],     qfh[ks], &bh4[0]);
                mma16816(accS[2 * nt + 1], qfh[ks], &bh4[2]);
                mma16816(accS[2 * nt],     qfh[ks], &bl4[0]);
                mma16816(accS[2 * nt + 1], qfh[ks], &bl4[2]);
                mma16816(accS[2 * nt],     qfl[ks], &bh4[0]);
                mma16816(accS[2 * nt + 1], qfl[ks], &bh4[2]);
            }
        }

        float pm[2] = {-3.0e38f, -3.0e38f};
        #pragma unroll
        for (int nf = 0; nf < 8; ++nf) {
            #pragma unroll
            for (int i2 = 0; i2 < 2; ++i2) {
                __half2 bb = *(__half2*)&braw[nf * 2 + i2];
                float s0 = accS[nf][i2 * 2 + 0] * inv + __half2float(bb.x);
                float s1 = accS[nf][i2 * 2 + 1] * inv + __half2float(bb.y);
                accS[nf][i2 * 2 + 0] = s0;
                accS[nf][i2 * 2 + 1] = s1;
                pm[i2] = fmaxf(pm[i2], fmaxf(s0, s1));
            }
        }
        #pragma unroll
        for (int i2 = 0; i2 < 2; ++i2) {
            pm[i2] = fmaxf(pm[i2], __shfl_xor_sync(0xffffffffu, pm[i2], 1));
            pm[i2] = fmaxf(pm[i2], __shfl_xor_sync(0xffffffffu, pm[i2], 2));
            float mnew = fmaxf(mrow[i2], pm[i2]);
            float sc = exp2f((mrow[i2] - mnew) * L2E);
            mrow[i2] = mnew;
            lrow[i2] *= sc;
            #pragma unroll
            for (int nf = 0; nf < 16; ++nf) {
                accO[nf][i2 * 2 + 0] *= sc;
                accO[nf][i2 * 2 + 1] *= sc;
            }
        }
        float psum[2] = {0.f, 0.f};
        #pragma unroll
        for (int nf = 0; nf < 8; ++nf) {
            #pragma unroll
            for (int i2 = 0; i2 < 2; ++i2) {
                float p0 = exp2f((accS[nf][i2 * 2 + 0] - mrow[i2]) * L2E);
                float p1 = exp2f((accS[nf][i2 * 2 + 1] - mrow[i2]) * L2E);
                accS[nf][i2 * 2 + 0] = p0;
                accS[nf][i2 * 2 + 1] = p1;
                psum[i2] += p0 + p1;
            }
        }
        #pragma unroll
        for (int i2 = 0; i2 < 2; ++i2) {
            psum[i2] += __shfl_xor_sync(0xffffffffu, psum[i2], 1);
            psum[i2] += __shfl_xor_sync(0xffffffffu, psum[i2], 2);
            lrow[i2] += psum[i2];
        }

        #pragma unroll
        for (int kk = 0; kk < 4; ++kk) {
            uint32_t pah[4], pal[4];
            #pragma unroll
            for (int hv = 0; hv < 2; ++hv) {
                const float v0 = accS[2 * kk + hv][0], v1 = accS[2 * kk + hv][1];
                const float v2 = accS[2 * kk + hv][2], v3 = accS[2 * kk + hv][3];
                pah[0 + hv * 2] = pack_h2(v0, v1);
                pah[1 + hv * 2] = pack_h2(v2, v3);
                __half2 h01 = *(__half2*)&pah[0 + hv * 2];
                __half2 h23 = *(__half2*)&pah[1 + hv * 2];
                pal[0 + hv * 2] = pack_h2(v0 - __half2float(h01.x),
                                          v1 - __half2float(h01.y));
                pal[1 + hv * 2] = pack_h2(v2 - __half2float(h23.x),
                                          v3 - __half2float(h23.y));
            }
            #pragma unroll
            for (int np = 0; np < 8; ++np) {
                uint32_t vh4[4], vl4[4];
                uint32_t bd = sb + FL_SVH + (kk * 16) * FL_QP + np * 32 + aoff;
                ldsm_x4_t(vh4, bd);
                ldsm_x4_t(vl4, bd + (FL_SVL - FL_SVH));
                mma16816(accO[2 * np],     pah, &vh4[0]);
                mma16816(accO[2 * np + 1], pah, &vh4[2]);
                mma16816(accO[2 * np],     pah, &vl4[0]);
                mma16816(accO[2 * np + 1], pah, &vl4[2]);
                mma16816(accO[2 * np],     pal, &vh4[0]);
                mma16816(accO[2 * np + 1], pal, &vh4[2]);
            }
        }
        __syncthreads();
    }

    float rp[2];
    rp[0] = 1.f / lrow[0];
    rp[1] = 1.f / lrow[1];
    #pragma unroll
    for (int nf = 0; nf < 16; ++nf) {
        #pragma unroll
        for (int i2 = 0; i2 < 2; ++i2) {
            float v0 = accO[nf][i2 * 2 + 0] * rp[i2];
            float v1 = accO[nf][i2 * 2 + 1] * rp[i2];
            long long o = ((long long)(qrow0 + 8 * i2) << 10) + h * 128 + nf * 8 + lq * 2;
            __half2 hh;
            hh.x = __float2half(v0);
            hh.y = __float2half(v1);
            *(__half2*)(ph + o) = hh;
        }
    }
}

// ===========================================================================
// fp16 1-product GEMM (dense): C[M x N] = A[M x K] * B[N x K]^T
// A and B both single fp16. CTA 128x128, BK=32, 8 warps, 4-stage cp.async.
// Stage: [A 10KB][B 10KB] = 20KB; 4 stages = 80KB; 2 CTAs/SM.
// 32 mmas per barrier (halves per-chunk overhead vs BK=16).
// EPI: 0 none | 1 resid+rowmask | 2 bias+relu | 3 bias+resid+rowmask
// OUT: 0 fp32 | 1 fp16 hi/lo pair | 2 fp16 single
// ===========================================================================
#define PITCH_B 80
#define TILE_B  (128 * PITCH_B)    // 10240
#define STAGE_B (2 * TILE_B)       // 20480
#define MG_SMEM (4 * STAGE_B)      // 81920

__device__ __forceinline__ void mg_load(
    uint32_t sb, const __half* __restrict__ A, const __half* __restrict__ Bw,
    int tid, int m0, int n0, int lda, int ldb, int koff)
{
    int seg = tid;
    #pragma unroll
    for (int i = 0; i < 2; ++i, seg += 256) {
        const int r = seg >> 2, s = seg & 3;
        cp16(sb + r * PITCH_B + s * 16,
             A + (long long)(m0 + r) * lda + koff + s * 8);
        cp16(sb + TILE_B + r * PITCH_B + s * 16,
             Bw + (long long)(n0 + r) * ldb + koff + s * 8);
    }
    cp_commit();
}

template <int EPI, int OUT>
__global__ void __launch_bounds__(256, 2)
mgemm_k(const __half* __restrict__ A, int lda,
        const __half* __restrict__ Bw, int ldb,
        float* Cf, __half* Ch, __half* Cl, int ldc,
        const float* __restrict__ resid, int ldr,
        const float* __restrict__ bias,
        const float* __restrict__ rowmask, int Kdim)
{
    extern __shared__ __align__(128) char smem[];
    const int tid = threadIdx.x, wid = tid >> 5, lane = tid & 31;
    const int m0 = blockIdx.y << 7, n0 = blockIdx.x << 7;
    const int wm = (wid >> 1) << 5;
    const int wn = (wid & 1) << 6;
    const uint32_t sb0 = smem_to_u32(smem);

    const uint32_t aoff = ((lane & 7) + ((lane >> 3) & 1) * 8) * PITCH_B + ((lane >> 4) & 1) * 16;
    const uint32_t boff = ((lane & 7) + ((lane >> 4) & 1) * 8) * PITCH_B + ((lane >> 3) & 1) * 16;

    float acc[2][8][4];
    #pragma unroll
    for (int i = 0; i < 2; ++i)
        #pragma unroll
        for (int j = 0; j < 8; ++j)
            #pragma unroll
            for (int k = 0; k < 4; ++k) acc[i][j][k] = 0.f;

    const int NC = Kdim >> 5;   // BK=32
    mg_load(sb0,               A, Bw, tid, m0, n0, lda, ldb, 0);
    mg_load(sb0 + STAGE_B,     A, Bw, tid, m0, n0, lda, ldb, 32);
    mg_load(sb0 + 2 * STAGE_B, A, Bw, tid, m0, n0, lda, ldb, 64);

    for (int kt = 0; kt < NC; ++kt) {
        if (kt + 2 < NC)      cp_wait2();
        else if (kt + 1 < NC) cp_wait1();
        else                  cp_wait0();
        __syncthreads();
        if (kt + 3 < NC)
            mg_load(sb0 + (uint32_t)((kt + 3) & 3) * STAGE_B,
                    A, Bw, tid, m0, n0, lda, ldb, (kt + 3) << 5);

        const uint32_t sA = sb0 + (uint32_t)(kt & 3) * STAGE_B;
        const uint32_t sB = sA + TILE_B;

        #pragma unroll
        for (int k0 = 0; k0 < 2; ++k0) {
            uint32_t a[2][4];
            #pragma unroll
            for (int mf = 0; mf < 2; ++mf)
                ldsm_x4(a[mf], sA + (wm + mf * 16) * PITCH_B + k0 * 32 + aoff);
            #pragma unroll
            for (int np = 0; np < 4; ++np) {
                uint32_t b4[4];
                ldsm_x4(b4, sB + (wn + np * 16) * PITCH_B + k0 * 32 + boff);
                #pragma unroll
                for (int mf = 0; mf < 2; ++mf) {
                    mma16816(acc[mf][2 * np],     a[mf], &b4[0]);
                    mma16816(acc[mf][2 * np + 1], a[mf], &b4[2]);
                }
            }
        }
    }

    const int lr = lane >> 2, lc2 = (lane & 3) << 1;
    #pragma unroll
    for (int mf = 0; mf < 2; ++mf) {
        #pragma unroll
        for (int h2 = 0; h2 < 2; ++h2) {
            const long long r = m0 + wm + mf * 16 + h2 * 8 + lr;
            float mfac = 1.f;
            if (EPI == 1 || EPI == 3) mfac = 1.f - rowmask[r];
            #pragma unroll
            for (int nf = 0; nf < 8; ++nf) {
                float v0 = acc[mf][nf][h2 * 2 + 0];
                float v1 = acc[mf][nf][h2 * 2 + 1];
                const long long c = n0 + wn + nf * 8 + lc2;
                if (EPI >= 2) { v0 += bias[c]; v1 += bias[c + 1]; }
                if (EPI == 2) { v0 = fmaxf(v0, 0.f); v1 = fmaxf(v1, 0.f); }
                if (EPI == 1 || EPI == 3) {
                    float2 rs = *(const float2*)(resid + r * ldr + c);
                    v0 = rs.x + v0 * mfac;
                    v1 = rs.y + v1 * mfac;
                }
                if (OUT == 0) {
                    float2 o; o.x = v0; o.y = v1;
                    *(float2*)(Cf + r * ldc + c) = o;
                } else if (OUT == 1) {
                    __half h0 = __float2half(v0), h1 = __float2half(v1);
                    __half2 hh, ll;
                    hh.x = h0; hh.y = h1;
                    ll.x = __float2half(v0 - __half2float(h0));
                    ll.y = __float2half(v1 - __half2float(h1));
                    *(__half2*)(Ch + r * ldc + c) = hh;
                    *(__half2*)(Cl + r * ldc + c) = ll;
                } else {
                    __half2 hh;
                    hh.x = __float2half(v0);
                    hh.y = __float2half(v1);
                    *(__half2*)(Ch + r * ldc + c) = hh;
                }
            }
        }
    }
}

// ===========================================================================
// Host orchestration
// ===========================================================================
extern "C" void kernel_launch(void* const* d_in, const int* in_sizes, int n_in,
                              void* d_out, int out_size)
{
    (void)in_sizes; (void)n_in; (void)out_size;

    const float* enc_out = (const float*)d_in[0];
    const float* x       = (const float*)d_in[1];
    const float* pmask   = (const float*)d_in[2];
    const float* qtself  = (const float*)d_in[3];
    const float* qtcross = (const float*)d_in[4];
    const float* swq = (const float*)d_in[5];
    const float* swk = (const float*)d_in[6];
    const float* swv = (const float*)d_in[7];
    const float* swo = (const float*)d_in[8];
    const float* cwq = (const float*)d_in[9];
    const float* cwk = (const float*)d_in[10];
    const float* cwv = (const float*)d_in[11];
    const float* cwo = (const float*)d_in[12];
    const float* w1  = (const float*)d_in[13];
    const float* b1  = (const float*)d_in[14];
    const float* w2  = (const float*)d_in[15];
    const float* b2  = (const float*)d_in[16];
    const float* ln1g = (const float*)d_in[17];
    const float* ln1b = (const float*)d_in[18];
    const float* ln2g = (const float*)d_in[19];
    const float* ln2b = (const float*)d_in[20];
    const float* ln3g = (const float*)d_in[21];
    const float* ln3b = (const float*)d_in[22];

    float* hb;
    cudaGetSymbolAddress((void**)&hb, g_h);

    __half *wqkvs, *wqkvc, *wos, *woc, *w1p, *w2p;
    __half *nh, *qkvh, *qkvl, *ph, *eh, *sh, *bs, *bc;
    cudaGetSymbolAddress((void**)&wqkvs, g_wqkvs);
    cudaGetSymbolAddress((void**)&wqkvc, g_wqkvc);
    cudaGetSymbolAddress((void**)&wos, g_wos);
    cudaGetSymbolAddress((void**)&woc, g_woc);
    cudaGetSymbolAddress((void**)&w1p, g_w1);
    cudaGetSymbolAddress((void**)&w2p, g_w2);
    cudaGetSymbolAddress((void**)&nh, g_nh);
    cudaGetSymbolAddress((void**)&qkvh, g_qkvh); cudaGetSymbolAddress((void**)&qkvl, g_qkvl);
    cudaGetSymbolAddress((void**)&ph, g_ph);
    cudaGetSymbolAddress((void**)&eh, g_eh);
    cudaGetSymbolAddress((void**)&sh, g_sh);
    cudaGetSymbolAddress((void**)&bs, g_bias_s); cudaGetSymbolAddress((void**)&bc, g_bias_c);

    cudaFuncSetAttribute(mgemm_k<0,1>, cudaFuncAttributeMaxDynamicSharedMemorySize, MG_SMEM);
    cudaFuncSetAttribute(mgemm_k<1,0>, cudaFuncAttributeMaxDynamicSharedMemorySize, MG_SMEM);
    cudaFuncSetAttribute(mgemm_k<2,2>, cudaFuncAttributeMaxDynamicSharedMemorySize, MG_SMEM);
    cudaFuncSetAttribute(mgemm_k<3,0>, cudaFuncAttributeMaxDynamicSharedMemorySize, MG_SMEM);
    cudaFuncSetAttribute(flash_k, cudaFuncAttributeMaxDynamicSharedMemorySize, FL_SMEM);

    // --- launch 1: h = x ---
    copy_k<<<BQ_ * M_ / 4 / 256, 256>>>((const float4*)x, (float4*)hb, BQ_ * M_ / 4);
    // --- launch 2: all weight transposes+converts ---
    {
        const long long sL = 3145728LL;
        const long long sH = 131072LL;
        TSAll a;
        auto set = [&](int i, const float* src, __half* hi,
                       int R, int C, int zs, long long s1, long long s2, long long s3, int Z) {
            a.d[i] = { src, hi, R, C, zs, s1, s2, s3, (C / 32) * (R / 32) * Z,
                       C / 32, R / 32 };
        };
        set(0, swq, wqkvs, M_, K_, 3, sL, sH, 0LL,        L_ * H_);
        set(1, swk, wqkvs, M_, K_, 3, sL, sH, 1048576LL,  L_ * H_);
        set(2, swv, wqkvs, M_, K_, 3, sL, sH, 2097152LL,  L_ * H_);
        set(3, cwq, wqkvc, M_, K_, 3, sL, sH, 0LL,        L_ * H_);
        set(4, cwk, wqkvc, M_, K_, 3, sL, sH, 1048576LL,  L_ * H_);
        set(5, cwv, wqkvc, M_, K_, 3, sL, sH, 2097152LL,  L_ * H_);
        set(6, swo, wos, H_ * V_, M_, 0, 1048576LL, 0LL, 0LL, L_);
        set(7, cwo, woc, H_ * V_, M_, 0, 1048576LL, 0LL, 0LL, L_);
        set(8, w1,  w1p, M_, F_, 0, 4194304LL, 0LL, 0LL, L_);
        set(9, w2,  w2p, F_, M_, 0, 4194304LL, 0LL, 0LL, L_);
        int total = 0;
        for (int i = 0; i < 10; ++i) total += a.d[i].tiles;
        tsplit_all_k<<<total, 256>>>(a);
    }

    const dim3 gQKV(3072 / 128, BQ_ / 128);
    const dim3 gPq (M_ / 128,  BQ_ / 128);
    const dim3 gKV (2048 / 128, BQ_ / 128);
    const dim3 gP  (M_ / 128,  BQ_ / 128);
    const dim3 gF1 (F_ / 128,  BQ_ / 128);
    const dim3 gFL (Q_ / 64, B_ * H_);
    const long long wS  = 3145728LL;
    const size_t wO  = 1048576;
    const size_t wLF = 4194304;

    for (int l = 0; l < L_; ++l) {
        for (int pass = 0; pass < 2; ++pass) {
            const bool self = (pass == 0);
            const float* lng = self ? ln1g : ln2g;
            const float* lnb = self ? ln1b : ln2b;
            __half* wcat = (self ? wqkvs : wqkvc) + l * wS;
            __half* wo_p = (self ? wos : woc) + l * wO;

            // l=0 self: LN is launch #3, QKV mgemm is #4 <- ncu target
            layernorm_h_k<<<BQ_, 256>>>(hb, lng + l * M_, lnb + l * M_, nh);
            if (self) {
                mgemm_k<0,1><<<gQKV, 256, MG_SMEM>>>(nh, M_, wcat, M_,
                                                     nullptr, qkvh, qkvl, 3072,
                                                     nullptr, 0, nullptr, nullptr, M_);
            } else {
                mgemm_k<0,1><<<gPq, 256, MG_SMEM>>>(nh, M_, wcat, M_,
                                                    nullptr, qkvh, qkvl, 3072,
                                                    nullptr, 0, nullptr, nullptr, M_);
                mgemm_k<0,1><<<gKV, 256, MG_SMEM>>>(eh, M_, wcat + 1048576, M_,
                                                    nullptr, qkvh + 1024, qkvl + 1024, 3072,
                                                    nullptr, 0, nullptr, nullptr, M_);
            }
            // deferred prep (first iteration only)
            if (l == 0 && self) {
                dim3 gb(B_ * Q_ * T_ / 2 / 256, 1, 2);
                bias_all_k<<<gb, 256>>>(pmask, qtself, qtcross, bs, bc);
                tohalf_k<<<B_ * T_ * M_ / 4 / 256, 256>>>(enc_out, eh, B_ * T_ * M_ / 4);
            }
            flash_k<<<gFL, 128, FL_SMEM>>>(qkvh, qkvl, self ? bs : bc, ph);
            mgemm_k<1,0><<<gP, 256, MG_SMEM>>>(ph, M_, wo_p, M_,
                                               hb, nullptr, nullptr, M_,
                                               hb, M_, nullptr, pmask, M_);
        }

        // ---- FFN ----
        layernorm_h_k<<<BQ_, 256>>>(hb, ln3g + l * M_, ln3b + l * M_, nh);
        mgemm_k<2,2><<<gF1, 256, MG_SMEM>>>(nh, M_, w1p + l * wLF, M_,
                                            nullptr, sh, nullptr, F_,
                                            nullptr, 0, b1 + l * F_, nullptr, M_);
        float* cdst = (l == L_ - 1) ? (float*)d_out : hb;
        mgemm_k<3,0><<<gP, 256, MG_SMEM>>>(sh, F_, w2p + l * wLF, F_,
                                           cdst, nullptr, nullptr, M_,
                                           hb, M_, b2 + l * M_, pmask, F_);
    }
}